// round 6
// baseline (speedup 1.0000x reference)
#include <cuda_runtime.h>
#include <math.h>

// ---------------- problem constants ----------------
#define B_   4
#define NQ_  1024
#define NK_  1024
#define C_   768
#define H_   12
#define DH_  64
#define M_   (B_*NQ_)        // 4096 rows for x-side, also B_*NK_ for y-side
#define HID_ (4*C_)          // 3072
#define SCALE_ 0.125f        // 64^-0.5

// ---------------- scratch (device globals; no allocation allowed) ----------------
__device__ float g_xn  [M_*C_];        // ln outputs (reused)
__device__ float g_yn  [M_*C_];
__device__ float g_qkv [M_*3*C_];      // self-attn qkv
__device__ float g_attn[M_*C_];        // attention outputs (reused)
__device__ float g_x   [M_*C_];        // running residual x
__device__ float g_cq  [M_*C_];
__device__ float g_ck  [M_*C_];
__device__ float g_cv  [M_*C_];
__device__ float g_mean[M_*NK_];       // head-mean of similarities [B,NQ,NK]
__device__ float g_hbuf[M_*HID_];      // MLP hidden

// ---------------- LayerNorm: one block per row, C=768, 256 threads ----------------
__global__ __launch_bounds__(256) void ln_kernel(const float* __restrict__ in,
                                                 const float* __restrict__ gw,
                                                 const float* __restrict__ bw,
                                                 float* __restrict__ out)
{
    int row = blockIdx.x;
    const float* p = in + (size_t)row * C_;
    int t = threadIdx.x;
    float x0 = p[t], x1 = p[t + 256], x2 = p[t + 512];
    float s  = x0 + x1 + x2;
    float sq = x0*x0 + x1*x1 + x2*x2;
    #pragma unroll
    for (int o = 16; o > 0; o >>= 1) {
        s  += __shfl_xor_sync(0xffffffffu, s,  o);
        sq += __shfl_xor_sync(0xffffffffu, sq, o);
    }
    __shared__ float ss[8], sqs[8];
    __shared__ float s_mean, s_inv;
    int w = t >> 5, lane = t & 31;
    if (lane == 0) { ss[w] = s; sqs[w] = sq; }
    __syncthreads();
    if (t == 0) {
        float S = 0.f, SQ = 0.f;
        #pragma unroll
        for (int i = 0; i < 8; i++) { S += ss[i]; SQ += sqs[i]; }
        float mean = S * (1.0f / C_);
        float var  = SQ * (1.0f / C_) - mean * mean;
        s_mean = mean;
        s_inv  = rsqrtf(var + 1e-5f);
    }
    __syncthreads();
    float mean = s_mean, inv = s_inv;
    float* o = out + (size_t)row * C_;
    o[t]       = (x0 - mean) * inv * gw[t]       + bw[t];
    o[t + 256] = (x1 - mean) * inv * gw[t + 256] + bw[t + 256];
    o[t + 512] = (x2 - mean) * inv * gw[t + 512] + bw[t + 512];
}

// ---------------- SGEMM NT: C[M,N] = A[M,K] @ B[N,K]^T (+bias)(gelu)(+R) ------------
// 128x128x16 tile, 256 threads, 8x8 micro (2x2 of 4x4 float4 quadrants).
// Double-buffered smem + register prefetch: ONE __syncthreads per K-iter.
// All M,N,K used here are multiples of 128/128/16 -> no bounds checks.
template<bool BIAS, bool RES, bool GELU>
__global__ __launch_bounds__(256) void gemm_nt(
    const float* __restrict__ A, const float* __restrict__ Bw,
    const float* __restrict__ bias, const float* __restrict__ R,
    float* __restrict__ Cc, int M, int N, int K)
{
    __shared__ float As[2][16][128];
    __shared__ float Bs[2][16][128];
    int bm = blockIdx.y * 128, bn = blockIdx.x * 128;
    int tid = threadIdx.x;
    int tx = tid & 15, ty = tid >> 4;

    float acc[8][8];
    #pragma unroll
    for (int i = 0; i < 8; i++)
        #pragma unroll
        for (int j = 0; j < 8; j++) acc[i][j] = 0.f;

    const float* Ag = A  + (size_t)bm * K;
    const float* Bg = Bw + (size_t)bn * K;

    // per-thread load coordinates (2 float4 from A, 2 from B per K-step)
    int lr[2], lc[2];
    #pragma unroll
    for (int i = 0; i < 2; i++) {
        int lin = tid + i * 256;        // 0..511 float4 slots
        lr[i] = lin >> 2;               // row 0..127
        lc[i] = (lin & 3) << 2;         // col 0,4,8,12
    }

    float4 ra[2], rb[2];
    // load tile 0 -> buffer 0
    #pragma unroll
    for (int i = 0; i < 2; i++) {
        ra[i] = *(const float4*)(Ag + (size_t)lr[i] * K + lc[i]);
        rb[i] = *(const float4*)(Bg + (size_t)lr[i] * K + lc[i]);
    }
    #pragma unroll
    for (int i = 0; i < 2; i++) {
        int r = lr[i], c = lc[i];
        As[0][c + 0][r] = ra[i].x; As[0][c + 1][r] = ra[i].y;
        As[0][c + 2][r] = ra[i].z; As[0][c + 3][r] = ra[i].w;
        Bs[0][c + 0][r] = rb[i].x; Bs[0][c + 1][r] = rb[i].y;
        Bs[0][c + 2][r] = rb[i].z; Bs[0][c + 3][r] = rb[i].w;
    }
    __syncthreads();

    int p = 0;
    for (int k0 = 0; k0 < K; k0 += 16) {
        bool more = (k0 + 16 < K);
        // prefetch next tile into registers
        if (more) {
            #pragma unroll
            for (int i = 0; i < 2; i++) {
                ra[i] = *(const float4*)(Ag + (size_t)lr[i] * K + k0 + 16 + lc[i]);
                rb[i] = *(const float4*)(Bg + (size_t)lr[i] * K + k0 + 16 + lc[i]);
            }
        }
        // compute on buffer p
        #pragma unroll
        for (int kk = 0; kk < 16; kk++) {
            float4 a0 = *(const float4*)&As[p][kk][ty * 4];
            float4 a1 = *(const float4*)&As[p][kk][64 + ty * 4];
            float4 b0 = *(const float4*)&Bs[p][kk][tx * 4];
            float4 b1 = *(const float4*)&Bs[p][kk][64 + tx * 4];
            float a[8] = {a0.x, a0.y, a0.z, a0.w, a1.x, a1.y, a1.z, a1.w};
            float b[8] = {b0.x, b0.y, b0.z, b0.w, b1.x, b1.y, b1.z, b1.w};
            #pragma unroll
            for (int i = 0; i < 8; i++)
                #pragma unroll
                for (int j = 0; j < 8; j++)
                    acc[i][j] += a[i] * b[j];
        }
        // store prefetched tile into the inactive buffer
        if (more) {
            int q = p ^ 1;
            #pragma unroll
            for (int i = 0; i < 2; i++) {
                int r = lr[i], c = lc[i];
                As[q][c + 0][r] = ra[i].x; As[q][c + 1][r] = ra[i].y;
                As[q][c + 2][r] = ra[i].z; As[q][c + 3][r] = ra[i].w;
                Bs[q][c + 0][r] = rb[i].x; Bs[q][c + 1][r] = rb[i].y;
                Bs[q][c + 2][r] = rb[i].z; Bs[q][c + 3][r] = rb[i].w;
            }
            __syncthreads();
            p = q;
        }
    }

    #pragma unroll
    for (int i = 0; i < 8; i++) {
        int row = bm + ((i < 4) ? (ty * 4 + i) : (64 + ty * 4 + (i - 4)));
        #pragma unroll
        for (int jh = 0; jh < 2; jh++) {
            int col = bn + jh * 64 + tx * 4;
            float v[4];
            #pragma unroll
            for (int j = 0; j < 4; j++) v[j] = acc[i][jh * 4 + j];
            if (BIAS) {
                #pragma unroll
                for (int j = 0; j < 4; j++) v[j] += bias[col + j];
            }
            if (GELU) {
                #pragma unroll
                for (int j = 0; j < 4; j++)
                    v[j] = 0.5f * v[j] * (1.0f + erff(v[j] * 0.70710678118654752f));
            }
            if (RES) {
                #pragma unroll
                for (int j = 0; j < 4; j++) v[j] += R[(size_t)row * N + col + j];
            }
            float4 o = make_float4(v[0], v[1], v[2], v[3]);
            *(float4*)(Cc + (size_t)row * N + col) = o;
        }
    }
}

// ---------------- head-mean of similarities: mean over H -> [B,NQ,NK] ----------------
__global__ __launch_bounds__(256) void sim_mean_kernel(const float* __restrict__ sim,
                                                       float* __restrict__ meanb)
{
    int bq = blockIdx.x;            // b*NQ + q
    int b  = bq >> 10;
    int q  = bq & 1023;
    for (int k = threadIdx.x; k < NK_; k += 256) {
        float s = 0.f;
        #pragma unroll
        for (int h = 0; h < H_; h++)
            s += sim[(((size_t)(b * H_ + h) * NQ_ + q) << 10) + k];
        meanb[((size_t)bq << 10) + k] = s * (1.0f / H_);
    }
}

// ---------------- self attention: 1 thread = 1 query, flash-style ----------------
__global__ __launch_bounds__(128) void attn_self_kernel(float* __restrict__ out)
{
    int qi = blockIdx.x * 128 + threadIdx.x;
    int h  = blockIdx.y, b = blockIdx.z;
    const float* qp = g_qkv + ((size_t)(b * NQ_ + qi)) * (3 * C_) + h * DH_;
    float q[64];
    #pragma unroll
    for (int i = 0; i < 64; i += 4) {
        float4 v = *(const float4*)(qp + i);
        q[i] = v.x * SCALE_; q[i+1] = v.y * SCALE_; q[i+2] = v.z * SCALE_; q[i+3] = v.w * SCALE_;
    }
    __shared__ float Ks[64][64];
    __shared__ float Vs[64][64];
    float acc[64];
    #pragma unroll
    for (int d = 0; d < 64; d++) acc[d] = 0.f;
    float m = -1e30f, l = 0.f;

    for (int k0 = 0; k0 < NK_; k0 += 64) {
        __syncthreads();
        #pragma unroll
        for (int i = 0; i < 8; i++) {
            int lin = threadIdx.x + i * 128;
            int r = lin >> 4, c = (lin & 15) << 2;
            const float* kp = g_qkv + ((size_t)(b * NQ_ + k0 + r)) * (3 * C_) + C_ + h * DH_ + c;
            *(float4*)&Ks[r][c] = *(const float4*)kp;
            *(float4*)&Vs[r][c] = *(const float4*)(kp + C_);
        }
        __syncthreads();
        for (int kk = 0; kk < 64; kk++) {
            float s0 = 0.f, s1 = 0.f, s2 = 0.f, s3 = 0.f;
            #pragma unroll
            for (int j = 0; j < 16; j++) {
                float4 kv = *(const float4*)&Ks[kk][j * 4];
                s0 += q[j*4+0] * kv.x; s1 += q[j*4+1] * kv.y;
                s2 += q[j*4+2] * kv.z; s3 += q[j*4+3] * kv.w;
            }
            float s = (s0 + s1) + (s2 + s3);
            float p;
            if (s > m) {
                float corr = __expf(m - s);
                l *= corr;
                #pragma unroll
                for (int d = 0; d < 64; d++) acc[d] *= corr;
                m = s; p = 1.f;
            } else {
                p = __expf(s - m);
            }
            l += p;
            #pragma unroll
            for (int d = 0; d < 64; d += 4) {
                float4 vv = *(const float4*)&Vs[kk][d];
                acc[d]   += p * vv.x; acc[d+1] += p * vv.y;
                acc[d+2] += p * vv.z; acc[d+3] += p * vv.w;
            }
        }
    }
    float inv = 1.f / l;
    float* op = out + ((size_t)(b * NQ_ + qi)) * C_ + h * DH_;
    #pragma unroll
    for (int d = 0; d < 64; d += 4) {
        float4 o = make_float4(acc[d] * inv, acc[d+1] * inv, acc[d+2] * inv, acc[d+3] * inv);
        *(float4*)(op + d) = o;
    }
}

// ---------------- cross attention with similarity bias + mask (mask = int32!) -------
__global__ __launch_bounds__(128) void attn_cross_kernel(const float* __restrict__ sims,
                                                         const int* __restrict__ mask,
                                                         float* __restrict__ out)
{
    int qi = blockIdx.x * 128 + threadIdx.x;
    int h  = blockIdx.y, b = blockIdx.z;
    const float* qp = g_cq + ((size_t)(b * NQ_ + qi)) * C_ + h * DH_;
    float q[64];
    #pragma unroll
    for (int i = 0; i < 64; i += 4) {
        float4 v = *(const float4*)(qp + i);
        q[i] = v.x * SCALE_; q[i+1] = v.y * SCALE_; q[i+2] = v.z * SCALE_; q[i+3] = v.w * SCALE_;
    }
    const float* simp  = sims  + ((size_t)(b * H_ + h) * NQ_ + qi) * NK_;
    const float* meanp = g_mean + ((size_t)(b * NQ_ + qi)) * NK_;
    const int*   maskp = mask + (size_t)qi * NK_;

    __shared__ float Ks[64][64];
    __shared__ float Vs[64][64];
    float acc[64];
    #pragma unroll
    for (int d = 0; d < 64; d++) acc[d] = 0.f;
    float m = -1e30f, l = 0.f;

    for (int k0 = 0; k0 < NK_; k0 += 64) {
        __syncthreads();
        #pragma unroll
        for (int i = 0; i < 8; i++) {
            int lin = threadIdx.x + i * 128;
            int r = lin >> 4, c = (lin & 15) << 2;
            size_t roff = ((size_t)(b * NK_ + k0 + r)) * C_ + h * DH_ + c;
            *(float4*)&Ks[r][c] = *(const float4*)(g_ck + roff);
            *(float4*)&Vs[r][c] = *(const float4*)(g_cv + roff);
        }
        __syncthreads();
        for (int kk = 0; kk < 64; kk++) {
            int kidx = k0 + kk;
            float s0 = 0.f, s1 = 0.f, s2 = 0.f, s3 = 0.f;
            #pragma unroll
            for (int j = 0; j < 16; j++) {
                float4 kv = *(const float4*)&Ks[kk][j * 4];
                s0 += q[j*4+0] * kv.x; s1 += q[j*4+1] * kv.y;
                s2 += q[j*4+2] * kv.z; s3 += q[j*4+3] * kv.w;
            }
            float s = (s0 + s1) + (s2 + s3) + simp[kidx] - meanp[kidx];
            if (maskp[kidx] == 0) s = -1e30f;
            float p;
            if (s > m) {
                float corr = __expf(m - s);
                l *= corr;
                #pragma unroll
                for (int d = 0; d < 64; d++) acc[d] *= corr;
                m = s; p = 1.f;
            } else {
                p = __expf(s - m);
            }
            l += p;
            #pragma unroll
            for (int d = 0; d < 64; d += 4) {
                float4 vv = *(const float4*)&Vs[kk][d];
                acc[d]   += p * vv.x; acc[d+1] += p * vv.y;
                acc[d+2] += p * vv.z; acc[d+3] += p * vv.w;
            }
        }
    }
    float inv = 1.f / l;
    float* op = out + ((size_t)(b * NQ_ + qi)) * C_ + h * DH_;
    #pragma unroll
    for (int d = 0; d < 64; d += 4) {
        float4 o = make_float4(acc[d] * inv, acc[d+1] * inv, acc[d+2] * inv, acc[d+3] * inv);
        *(float4*)(op + d) = o;
    }
}

// ---------------- float4 copy (y passthrough) ----------------
__global__ void copy4_kernel(const float4* __restrict__ in, float4* __restrict__ out, int n4)
{
    int i = blockIdx.x * 256 + threadIdx.x;
    if (i < n4) out[i] = in[i];
}

// ---------------- launch ----------------
extern "C" void kernel_launch(void* const* d_in, const int* in_sizes, int n_in,
                              void* d_out, int out_size)
{
    const float* x      = (const float*)d_in[0];
    const float* y      = (const float*)d_in[1];
    // d_in[2]=xpos, d_in[3]=ypos unused
    const int*   mask   = (const int*)d_in[4];     // bool serialized as int32
    const float* sims   = (const float*)d_in[5];
    const float* ln1_g  = (const float*)d_in[6];
    const float* ln1_b  = (const float*)d_in[7];
    const float* ln2_g  = (const float*)d_in[8];
    const float* ln2_b  = (const float*)d_in[9];
    const float* ln3_g  = (const float*)d_in[10];
    const float* ln3_b  = (const float*)d_in[11];
    const float* lny_g  = (const float*)d_in[12];
    const float* lny_b  = (const float*)d_in[13];
    const float* qkv_w  = (const float*)d_in[14];
    const float* aproj_w= (const float*)d_in[15];
    const float* aproj_b= (const float*)d_in[16];
    const float* pq_w   = (const float*)d_in[17];
    const float* pk_w   = (const float*)d_in[18];
    const float* pv_w   = (const float*)d_in[19];
    const float* cproj_w= (const float*)d_in[20];
    const float* cproj_b= (const float*)d_in[21];
    const float* fc1_w  = (const float*)d_in[22];
    const float* fc1_b  = (const float*)d_in[23];
    const float* fc2_w  = (const float*)d_in[24];
    const float* fc2_b  = (const float*)d_in[25];

    float* out_x = (float*)d_out;
    float* out_y = out_x + (size_t)M_ * C_;

    float *xn, *yn, *qkv, *attn, *gx, *cq, *ck, *cv, *meanb, *hbuf;
    cudaGetSymbolAddress((void**)&xn,    g_xn);
    cudaGetSymbolAddress((void**)&yn,    g_yn);
    cudaGetSymbolAddress((void**)&qkv,   g_qkv);
    cudaGetSymbolAddress((void**)&attn,  g_attn);
    cudaGetSymbolAddress((void**)&gx,    g_x);
    cudaGetSymbolAddress((void**)&cq,    g_cq);
    cudaGetSymbolAddress((void**)&ck,    g_ck);
    cudaGetSymbolAddress((void**)&cv,    g_cv);
    cudaGetSymbolAddress((void**)&meanb, g_mean);
    cudaGetSymbolAddress((void**)&hbuf,  g_hbuf);

    // 1. xn = LN(x)
    ln_kernel<<<M_, 256>>>(x, ln1_g, ln1_b, xn);
    // 2. qkv = xn @ qkv_w^T
    gemm_nt<false,false,false><<<dim3(3*C_/128, M_/128), 256>>>(xn, qkv_w, nullptr, nullptr, qkv, M_, 3*C_, C_);
    // 3. self attention -> attn
    attn_self_kernel<<<dim3(NQ_/128, H_, B_), 128>>>(attn);
    // 4. x = x + attn @ aproj_w^T + aproj_b  -> gx
    gemm_nt<true,true,false><<<dim3(C_/128, M_/128), 256>>>(attn, aproj_w, aproj_b, x, gx, M_, C_, C_);
    // 5. yn = LN(y); xn = LN(gx)
    ln_kernel<<<M_, 256>>>(y,  lny_g, lny_b, yn);
    ln_kernel<<<M_, 256>>>(gx, ln2_g, ln2_b, xn);
    // 6. cross projections
    gemm_nt<false,false,false><<<dim3(C_/128, M_/128), 256>>>(xn, pq_w, nullptr, nullptr, cq, M_, C_, C_);
    gemm_nt<false,false,false><<<dim3(C_/128, M_/128), 256>>>(yn, pk_w, nullptr, nullptr, ck, M_, C_, C_);
    gemm_nt<false,false,false><<<dim3(C_/128, M_/128), 256>>>(yn, pv_w, nullptr, nullptr, cv, M_, C_, C_);
    // 7. head-mean of similarities
    sim_mean_kernel<<<M_, 256>>>(sims, meanb);
    // 8. cross attention -> attn
    attn_cross_kernel<<<dim3(NQ_/128, H_, B_), 128>>>(sims, mask, attn);
    // 9. x = x + attn @ cproj_w^T + cproj_b  (in place on gx)
    gemm_nt<true,true,false><<<dim3(C_/128, M_/128), 256>>>(attn, cproj_w, cproj_b, gx, gx, M_, C_, C_);
    // 10. xn = LN(gx)
    ln_kernel<<<M_, 256>>>(gx, ln3_g, ln3_b, xn);
    // 11. h = gelu(xn @ fc1_w^T + fc1_b)
    gemm_nt<true,false,true><<<dim3(HID_/128, M_/128), 256>>>(xn, fc1_w, fc1_b, nullptr, hbuf, M_, HID_, C_);
    // 12. out_x = gx + h @ fc2_w^T + fc2_b
    gemm_nt<true,true,false><<<dim3(C_/128, M_/128), 256>>>(hbuf, fc2_w, fc2_b, gx, out_x, M_, C_, HID_);
    // 13. out_y = y
    copy4_kernel<<<(M_*C_/4 + 255)/256, 256>>>((const float4*)y, (float4*)out_y, M_*C_/4);
}

// round 11
// speedup vs baseline: 1.3481x; 1.3481x over previous
#include <cuda_runtime.h>
#include <cuda_bf16.h>
#include <math.h>
#include <stdint.h>

// ---------------- problem constants ----------------
#define B_   4
#define NQ_  1024
#define NK_  1024
#define C_   768
#define H_   12
#define DH_  64
#define M_   (B_*NQ_)        // 4096
#define HID_ (4*C_)          // 3072
#define SCALE_ 0.125f

// ---------------- scratch (device globals; no allocation allowed) ----------------
__device__ __align__(256) float g_xn  [M_*C_];
__device__ __align__(256) float g_yn  [M_*C_];
__device__ __align__(256) float g_qkv [M_*3*C_];
__device__ __align__(256) float g_attn[M_*C_];
__device__ __align__(256) float g_x   [M_*C_];
__device__ __align__(256) float g_cq  [M_*C_];
__device__ __align__(256) float g_ck  [M_*C_];
__device__ __align__(256) float g_cv  [M_*C_];
__device__ __align__(256) float g_mean[M_*NK_];
__device__ __align__(256) float g_hbuf[M_*HID_];
// split-bf16 operands (16B-aligned: loaded as uint4)
__device__ __align__(256) __nv_bfloat16 g_ah[M_*HID_];     // A hi
__device__ __align__(256) __nv_bfloat16 g_al[M_*HID_];     // A lo
__device__ __align__(256) __nv_bfloat16 g_bh[HID_*C_];     // B hi
__device__ __align__(256) __nv_bfloat16 g_bl[HID_*C_];     // B lo

// ---------------- helpers ----------------
__device__ __forceinline__ uint32_t smem_u32(const void* p) {
    uint32_t a;
    asm("{ .reg .u64 t; cvta.to.shared.u64 t, %1; cvt.u32.u64 %0, t; }" : "=r"(a) : "l"(p));
    return a;
}
__device__ __forceinline__ void ldm_x4(uint32_t* r, uint32_t addr) {
    asm volatile("ldmatrix.sync.aligned.m8n8.x4.shared.b16 {%0,%1,%2,%3}, [%4];"
        : "=r"(r[0]), "=r"(r[1]), "=r"(r[2]), "=r"(r[3]) : "r"(addr));
}
__device__ __forceinline__ void mma_bf16(float* c, const uint32_t* a, const uint32_t* b) {
    asm volatile("mma.sync.aligned.m16n8k16.row.col.f32.bf16.bf16.f32 "
        "{%0,%1,%2,%3}, {%4,%5,%6,%7}, {%8,%9}, {%0,%1,%2,%3};"
        : "+f"(c[0]), "+f"(c[1]), "+f"(c[2]), "+f"(c[3])
        : "r"(a[0]), "r"(a[1]), "r"(a[2]), "r"(a[3]), "r"(b[0]), "r"(b[1]));
}

// ---------------- fp32 -> (hi,lo) bf16 split ----------------
__global__ __launch_bounds__(256) void cvt_split(const float* __restrict__ in,
                                                 __nv_bfloat16* __restrict__ hi,
                                                 __nv_bfloat16* __restrict__ lo, int n4)
{
    int i = blockIdx.x * 256 + threadIdx.x;
    if (i >= n4) return;
    float4 v = ((const float4*)in)[i];
    __nv_bfloat16 h0 = __float2bfloat16(v.x), h1 = __float2bfloat16(v.y);
    __nv_bfloat16 h2 = __float2bfloat16(v.z), h3 = __float2bfloat16(v.w);
    __nv_bfloat16 l0 = __float2bfloat16(v.x - __bfloat162float(h0));
    __nv_bfloat16 l1 = __float2bfloat16(v.y - __bfloat162float(h1));
    __nv_bfloat16 l2 = __float2bfloat16(v.z - __bfloat162float(h2));
    __nv_bfloat16 l3 = __float2bfloat16(v.w - __bfloat162float(h3));
    ((__nv_bfloat162*)hi)[2*i]   = __halves2bfloat162(h0, h1);
    ((__nv_bfloat162*)hi)[2*i+1] = __halves2bfloat162(h2, h3);
    ((__nv_bfloat162*)lo)[2*i]   = __halves2bfloat162(l0, l1);
    ((__nv_bfloat162*)lo)[2*i+1] = __halves2bfloat162(l2, l3);
}

// ---------------- HMMA split-bf16 GEMM NT ---------------------------------------
// C[M,N] = A[M,K] @ B[N,K]^T via Ah*Bh + Ah*Bl + Al*Bh, fp32 accum.
// 256 threads, 128x128 CTA tile, warp = 64x32, BK=32 (smem rows padded to 40).
#define BKP 40   // padded row length (elements); row stride = 80B (16B-aligned)

template<bool BIAS, bool RES, bool GELU>
__global__ __launch_bounds__(256) void tgemm(
    const __nv_bfloat16* __restrict__ Ah, const __nv_bfloat16* __restrict__ Al,
    const __nv_bfloat16* __restrict__ Bh, const __nv_bfloat16* __restrict__ Bl,
    const float* __restrict__ bias, const float* __restrict__ R,
    float* __restrict__ Cc, int M, int N, int K)
{
    __shared__ __align__(16) __nv_bfloat16 sAh[128 * BKP];
    __shared__ __align__(16) __nv_bfloat16 sAl[128 * BKP];
    __shared__ __align__(16) __nv_bfloat16 sBh[128 * BKP];
    __shared__ __align__(16) __nv_bfloat16 sBl[128 * BKP];

    int tid  = threadIdx.x;
    int wid  = tid >> 5, lane = tid & 31;
    int wm   = wid & 1;          // 0..1  -> m half (64 rows)
    int wn   = wid >> 1;         // 0..3  -> n quarter (32 cols)
    int bm = blockIdx.y * 128, bn = blockIdx.x * 128;

    float acc[4][4][4];          // [m-tile][n-tile][4 c-regs]
    #pragma unroll
    for (int i = 0; i < 4; i++)
        #pragma unroll
        for (int j = 0; j < 4; j++)
            #pragma unroll
            for (int q = 0; q < 4; q++) acc[i][j][q] = 0.f;

    uint32_t uAh = smem_u32(sAh), uAl = smem_u32(sAl);
    uint32_t uBh = smem_u32(sBh), uBl = smem_u32(sBl);

    // ldmatrix per-lane address components
    int arow = lane & 15;              // row within 16-row group
    int ahalf = (lane >> 4) << 3;      // +0 / +8 elements in k

    for (int kt = 0; kt < K; kt += 32) {
        // ---- load 4 tiles of 128x32 bf16 into padded smem ----
        #pragma unroll
        for (int i = 0; i < 8; i++) {
            int idx = tid + i * 256;           // 0..2047 uint4 slots
            int a   = idx >> 9;                // which array (512 each)
            int wi  = idx & 511;
            int row = wi >> 2, c = wi & 3;     // c: 0..3 (8 elements each)
            const __nv_bfloat16* src = (a == 0) ? Ah : (a == 1) ? Al : (a == 2) ? Bh : Bl;
            int gr = ((a < 2) ? bm : bn) + row;
            uint4 v = *(const uint4*)(src + (size_t)gr * K + kt + c * 8);
            __nv_bfloat16* dst = (a == 0) ? sAh : (a == 1) ? sAl : (a == 2) ? sBh : sBl;
            *(uint4*)(dst + row * BKP + c * 8) = v;
        }
        __syncthreads();

        #pragma unroll
        for (int ks = 0; ks < 32; ks += 16) {
            // A fragments: 4 m-tiles, hi and lo
            uint32_t ah[4][4], al[4][4];
            #pragma unroll
            for (int mt = 0; mt < 4; mt++) {
                uint32_t off = ((wm * 64 + mt * 16 + arow) * BKP + ks + ahalf) * 2;
                ldm_x4(ah[mt], uAh + off);
                ldm_x4(al[mt], uAl + off);
            }
            // B fragments: 4 n-tiles from 2 x4-loads (16 n-rows each), hi and lo
            uint32_t bh[4][2], bl[4][2];
            #pragma unroll
            for (int nb = 0; nb < 2; nb++) {
                uint32_t off = ((wn * 32 + nb * 16 + arow) * BKP + ks + ahalf) * 2;
                uint32_t q[4];
                ldm_x4(q, uBh + off);
                bh[nb*2+0][0] = q[0]; bh[nb*2+0][1] = q[2];
                bh[nb*2+1][0] = q[1]; bh[nb*2+1][1] = q[3];
                ldm_x4(q, uBl + off);
                bl[nb*2+0][0] = q[0]; bl[nb*2+0][1] = q[2];
                bl[nb*2+1][0] = q[1]; bl[nb*2+1][1] = q[3];
            }
            // 3-term MMA
            #pragma unroll
            for (int mt = 0; mt < 4; mt++)
                #pragma unroll
                for (int nt = 0; nt < 4; nt++) {
                    mma_bf16(acc[mt][nt], ah[mt], bh[nt]);
                    mma_bf16(acc[mt][nt], ah[mt], bl[nt]);
                    mma_bf16(acc[mt][nt], al[mt], bh[nt]);
                }
        }
        __syncthreads();
    }

    // ---- epilogue ----
    #pragma unroll
    for (int mt = 0; mt < 4; mt++) {
        #pragma unroll
        for (int nt = 0; nt < 4; nt++) {
            int m0 = bm + wm * 64 + mt * 16 + (lane >> 2);
            int n0 = bn + wn * 32 + nt * 8 + (lane & 3) * 2;
            #pragma unroll
            for (int half = 0; half < 2; half++) {
                int m = m0 + half * 8;
                float v0 = acc[mt][nt][half * 2 + 0];
                float v1 = acc[mt][nt][half * 2 + 1];
                if (BIAS) { v0 += bias[n0]; v1 += bias[n0 + 1]; }
                if (GELU) {
                    v0 = 0.5f * v0 * (1.0f + erff(v0 * 0.70710678118654752f));
                    v1 = 0.5f * v1 * (1.0f + erff(v1 * 0.70710678118654752f));
                }
                if (RES) {
                    v0 += R[(size_t)m * N + n0];
                    v1 += R[(size_t)m * N + n0 + 1];
                }
                *(float2*)(Cc + (size_t)m * N + n0) = make_float2(v0, v1);
            }
        }
    }
}

// ---------------- LayerNorm ----------------
__global__ __launch_bounds__(256) void ln_kernel(const float* __restrict__ in,
                                                 const float* __restrict__ gw,
                                                 const float* __restrict__ bw,
                                                 float* __restrict__ out)
{
    int row = blockIdx.x;
    const float* p = in + (size_t)row * C_;
    int t = threadIdx.x;
    float x0 = p[t], x1 = p[t + 256], x2 = p[t + 512];
    float s  = x0 + x1 + x2;
    float sq = x0*x0 + x1*x1 + x2*x2;
    #pragma unroll
    for (int o = 16; o > 0; o >>= 1) {
        s  += __shfl_xor_sync(0xffffffffu, s,  o);
        sq += __shfl_xor_sync(0xffffffffu, sq, o);
    }
    __shared__ float ss[8], sqs[8];
    __shared__ float s_mean, s_inv;
    int w = t >> 5, lane = t & 31;
    if (lane == 0) { ss[w] = s; sqs[w] = sq; }
    __syncthreads();
    if (t == 0) {
        float S = 0.f, SQ = 0.f;
        #pragma unroll
        for (int i = 0; i < 8; i++) { S += ss[i]; SQ += sqs[i]; }
        float mean = S * (1.0f / C_);
        float var  = SQ * (1.0f / C_) - mean * mean;
        s_mean = mean;
        s_inv  = rsqrtf(var + 1e-5f);
    }
    __syncthreads();
    float mean = s_mean, inv = s_inv;
    float* o = out + (size_t)row * C_;
    o[t]       = (x0 - mean) * inv * gw[t]       + bw[t];
    o[t + 256] = (x1 - mean) * inv * gw[t + 256] + bw[t + 256];
    o[t + 512] = (x2 - mean) * inv * gw[t + 512] + bw[t + 512];
}

// ---------------- head-mean of similarities ----------------
__global__ __launch_bounds__(256) void sim_mean_kernel(const float* __restrict__ sim,
                                                       float* __restrict__ meanb)
{
    int bq = blockIdx.x;
    int b  = bq >> 10;
    int q  = bq & 1023;
    for (int k = threadIdx.x; k < NK_; k += 256) {
        float s = 0.f;
        #pragma unroll
        for (int h = 0; h < H_; h++)
            s += sim[(((size_t)(b * H_ + h) * NQ_ + q) << 10) + k];
        meanb[((size_t)bq << 10) + k] = s * (1.0f / H_);
    }
}

// ---------------- self attention (flash-style, 1 thread = 1 query) ----------------
__global__ __launch_bounds__(128) void attn_self_kernel(float* __restrict__ out)
{
    int qi = blockIdx.x * 128 + threadIdx.x;
    int h  = blockIdx.y, b = blockIdx.z;
    const float* qp = g_qkv + ((size_t)(b * NQ_ + qi)) * (3 * C_) + h * DH_;
    float q[64];
    #pragma unroll
    for (int i = 0; i < 64; i += 4) {
        float4 v = *(const float4*)(qp + i);
        q[i] = v.x * SCALE_; q[i+1] = v.y * SCALE_; q[i+2] = v.z * SCALE_; q[i+3] = v.w * SCALE_;
    }
    __shared__ float Ks[64][64];
    __shared__ float Vs[64][64];
    float acc[64];
    #pragma unroll
    for (int d = 0; d < 64; d++) acc[d] = 0.f;
    float m = -1e30f, l = 0.f;

    for (int k0 = 0; k0 < NK_; k0 += 64) {
        __syncthreads();
        #pragma unroll
        for (int i = 0; i < 8; i++) {
            int lin = threadIdx.x + i * 128;
            int r = lin >> 4, c = (lin & 15) << 2;
            const float* kp = g_qkv + ((size_t)(b * NQ_ + k0 + r)) * (3 * C_) + C_ + h * DH_ + c;
            *(float4*)&Ks[r][c] = *(const float4*)kp;
            *(float4*)&Vs[r][c] = *(const float4*)(kp + C_);
        }
        __syncthreads();
        for (int kk = 0; kk < 64; kk++) {
            float s0 = 0.f, s1 = 0.f, s2 = 0.f, s3 = 0.f;
            #pragma unroll
            for (int j = 0; j < 16; j++) {
                float4 kv = *(const float4*)&Ks[kk][j * 4];
                s0 += q[j*4+0] * kv.x; s1 += q[j*4+1] * kv.y;
                s2 += q[j*4+2] * kv.z; s3 += q[j*4+3] * kv.w;
            }
            float s = (s0 + s1) + (s2 + s3);
            float p;
            if (s > m) {
                float corr = __expf(m - s);
                l *= corr;
                #pragma unroll
                for (int d = 0; d < 64; d++) acc[d] *= corr;
                m = s; p = 1.f;
            } else {
                p = __expf(s - m);
            }
            l += p;
            #pragma unroll
            for (int d = 0; d < 64; d += 4) {
                float4 vv = *(const float4*)&Vs[kk][d];
                acc[d]   += p * vv.x; acc[d+1] += p * vv.y;
                acc[d+2] += p * vv.z; acc[d+3] += p * vv.w;
            }
        }
    }
    float inv = 1.f / l;
    float* op = out + ((size_t)(b * NQ_ + qi)) * C_ + h * DH_;
    #pragma unroll
    for (int d = 0; d < 64; d += 4) {
        float4 o = make_float4(acc[d] * inv, acc[d+1] * inv, acc[d+2] * inv, acc[d+3] * inv);
        *(float4*)(op + d) = o;
    }
}

// ---------------- cross attention with similarity bias + int32 mask ----------------
__global__ __launch_bounds__(128) void attn_cross_kernel(const float* __restrict__ sims,
                                                         const int* __restrict__ mask,
                                                         float* __restrict__ out)
{
    int qi = blockIdx.x * 128 + threadIdx.x;
    int h  = blockIdx.y, b = blockIdx.z;
    const float* qp = g_cq + ((size_t)(b * NQ_ + qi)) * C_ + h * DH_;
    float q[64];
    #pragma unroll
    for (int i = 0; i < 64; i += 4) {
        float4 v = *(const float4*)(qp + i);
        q[i] = v.x * SCALE_; q[i+1] = v.y * SCALE_; q[i+2] = v.z * SCALE_; q[i+3] = v.w * SCALE_;
    }
    const float* simp  = sims  + ((size_t)(b * H_ + h) * NQ_ + qi) * NK_;
    const float* meanp = g_mean + ((size_t)(b * NQ_ + qi)) * NK_;
    const int*   maskp = mask + (size_t)qi * NK_;

    __shared__ float Ks[64][64];
    __shared__ float Vs[64][64];
    float acc[64];
    #pragma unroll
    for (int d = 0; d < 64; d++) acc[d] = 0.f;
    float m = -1e30f, l = 0.f;

    for (int k0 = 0; k0 < NK_; k0 += 64) {
        __syncthreads();
        #pragma unroll
        for (int i = 0; i < 8; i++) {
            int lin = threadIdx.x + i * 128;
            int r = lin >> 4, c = (lin & 15) << 2;
            size_t roff = ((size_t)(b * NK_ + k0 + r)) * C_ + h * DH_ + c;
            *(float4*)&Ks[r][c] = *(const float4*)(g_ck + roff);
            *(float4*)&Vs[r][c] = *(const float4*)(g_cv + roff);
        }
        __syncthreads();
        for (int kk = 0; kk < 64; kk++) {
            int kidx = k0 + kk;
            float s0 = 0.f, s1 = 0.f, s2 = 0.f, s3 = 0.f;
            #pragma unroll
            for (int j = 0; j < 16; j++) {
                float4 kv = *(const float4*)&Ks[kk][j * 4];
                s0 += q[j*4+0] * kv.x; s1 += q[j*4+1] * kv.y;
                s2 += q[j*4+2] * kv.z; s3 += q[j*4+3] * kv.w;
            }
            float s = (s0 + s1) + (s2 + s3) + simp[kidx] - meanp[kidx];
            if (maskp[kidx] == 0) s = -1e30f;
            float p;
            if (s > m) {
                float corr = __expf(m - s);
                l *= corr;
                #pragma unroll
                for (int d = 0; d < 64; d++) acc[d] *= corr;
                m = s; p = 1.f;
            } else {
                p = __expf(s - m);
            }
            l += p;
            #pragma unroll
            for (int d = 0; d < 64; d += 4) {
                float4 vv = *(const float4*)&Vs[kk][d];
                acc[d]   += p * vv.x; acc[d+1] += p * vv.y;
                acc[d+2] += p * vv.z; acc[d+3] += p * vv.w;
            }
        }
    }
    float inv = 1.f / l;
    float* op = out + ((size_t)(b * NQ_ + qi)) * C_ + h * DH_;
    #pragma unroll
    for (int d = 0; d < 64; d += 4) {
        float4 o = make_float4(acc[d] * inv, acc[d+1] * inv, acc[d+2] * inv, acc[d+3] * inv);
        *(float4*)(op + d) = o;
    }
}

// ---------------- float4 copy ----------------
__global__ void copy4_kernel(const float4* __restrict__ in, float4* __restrict__ out, int n4)
{
    int i = blockIdx.x * 256 + threadIdx.x;
    if (i < n4) out[i] = in[i];
}

// ---------------- launch ----------------
static inline void cvt(const float* in, __nv_bfloat16* hi, __nv_bfloat16* lo, int n)
{
    int n4 = n / 4;
    cvt_split<<<n4 / 256, 256>>>(in, hi, lo, n4);
}

extern "C" void kernel_launch(void* const* d_in, const int* in_sizes, int n_in,
                              void* d_out, int out_size)
{
    const float* x      = (const float*)d_in[0];
    const float* y      = (const float*)d_in[1];
    const int*   mask   = (const int*)d_in[4];
    const float* sims   = (const float*)d_in[5];
    const float* ln1_g  = (const float*)d_in[6];
    const float* ln1_b  = (const float*)d_in[7];
    const float* ln2_g  = (const float*)d_in[8];
    const float* ln2_b  = (const float*)d_in[9];
    const float* ln3_g  = (const float*)d_in[10];
    const float* ln3_b  = (const float*)d_in[11];
    const float* lny_g  = (const float*)d_in[12];
    const float* lny_b  = (const float*)d_in[13];
    const float* qkv_w  = (const float*)d_in[14];
    const float* aproj_w= (const float*)d_in[15];
    const float* aproj_b= (const float*)d_in[16];
    const float* pq_w   = (const float*)d_in[17];
    const float* pk_w   = (const float*)d_in[18];
    const float* pv_w   = (const float*)d_in[19];
    const float* cproj_w= (const float*)d_in[20];
    const float* cproj_b= (const float*)d_in[21];
    const float* fc1_w  = (const float*)d_in[22];
    const float* fc1_b  = (const float*)d_in[23];
    const float* fc2_w  = (const float*)d_in[24];
    const float* fc2_b  = (const float*)d_in[25];

    float* out_x = (float*)d_out;
    float* out_y = out_x + (size_t)M_ * C_;

    float *xn, *yn, *qkv, *attn, *gx, *cq, *ck, *cv, *meanb, *hbuf;
    __nv_bfloat16 *ah, *al, *bh, *bl;
    cudaGetSymbolAddress((void**)&xn,    g_xn);
    cudaGetSymbolAddress((void**)&yn,    g_yn);
    cudaGetSymbolAddress((void**)&qkv,   g_qkv);
    cudaGetSymbolAddress((void**)&attn,  g_attn);
    cudaGetSymbolAddress((void**)&gx,    g_x);
    cudaGetSymbolAddress((void**)&cq,    g_cq);
    cudaGetSymbolAddress((void**)&ck,    g_ck);
    cudaGetSymbolAddress((void**)&cv,    g_cv);
    cudaGetSymbolAddress((void**)&meanb, g_mean);
    cudaGetSymbolAddress((void**)&hbuf,  g_hbuf);
    cudaGetSymbolAddress((void**)&ah,    g_ah);
    cudaGetSymbolAddress((void**)&al,    g_al);
    cudaGetSymbolAddress((void**)&bh,    g_bh);
    cudaGetSymbolAddress((void**)&bl,    g_bl);

    // 1. xn = LN(x); qkv = xn @ qkv_w^T
    ln_kernel<<<M_, 256>>>(x, ln1_g, ln1_b, xn);
    cvt(xn, ah, al, M_ * C_);
    cvt(qkv_w, bh, bl, 3 * C_ * C_);
    tgemm<false,false,false><<<dim3(3*C_/128, M_/128), 256>>>(ah, al, bh, bl, nullptr, nullptr, qkv, M_, 3*C_, C_);
    // 2. self attention
    attn_self_kernel<<<dim3(NQ_/128, H_, B_), 128>>>(attn);
    // 3. gx = x + attn @ aproj_w^T + aproj_b
    cvt(attn, ah, al, M_ * C_);
    cvt(aproj_w, bh, bl, C_ * C_);
    tgemm<true,true,false><<<dim3(C_/128, M_/128), 256>>>(ah, al, bh, bl, aproj_b, x, gx, M_, C_, C_);
    // 4. norms
    ln_kernel<<<M_, 256>>>(y,  lny_g, lny_b, yn);
    ln_kernel<<<M_, 256>>>(gx, ln2_g, ln2_b, xn);
    // 5. cross projections
    cvt(xn, ah, al, M_ * C_);
    cvt(pq_w, bh, bl, C_ * C_);
    tgemm<false,false,false><<<dim3(C_/128, M_/128), 256>>>(ah, al, bh, bl, nullptr, nullptr, cq, M_, C_, C_);
    cvt(yn, ah, al, M_ * C_);
    cvt(pk_w, bh, bl, C_ * C_);
    tgemm<false,false,false><<<dim3(C_/128, M_/128), 256>>>(ah, al, bh, bl, nullptr, nullptr, ck, M_, C_, C_);
    cvt(pv_w, bh, bl, C_ * C_);
    tgemm<false,false,false><<<dim3(C_/128, M_/128), 256>>>(ah, al, bh, bl, nullptr, nullptr, cv, M_, C_, C_);
    // 6. cross attention
    sim_mean_kernel<<<M_, 256>>>(sims, meanb);
    attn_cross_kernel<<<dim3(NQ_/128, H_, B_), 128>>>(sims, mask, attn);
    // 7. gx = gx + attn @ cproj_w^T + cproj_b
    cvt(attn, ah, al, M_ * C_);
    cvt(cproj_w, bh, bl, C_ * C_);
    tgemm<true,true,false><<<dim3(C_/128, M_/128), 256>>>(ah, al, bh, bl, cproj_b, gx, gx, M_, C_, C_);
    // 8. MLP
    ln_kernel<<<M_, 256>>>(gx, ln3_g, ln3_b, xn);
    cvt(xn, ah, al, M_ * C_);
    cvt(fc1_w, bh, bl, HID_ * C_);
    tgemm<true,false,true><<<dim3(HID_/128, M_/128), 256>>>(ah, al, bh, bl, fc1_b, nullptr, hbuf, M_, HID_, C_);
    cvt(hbuf, ah, al, M_ * HID_);
    cvt(fc2_w, bh, bl, C_ * HID_);
    tgemm<true,true,false><<<dim3(C_/128, M_/128), 256>>>(ah, al, bh, bl, fc2_b, gx, out_x, M_, C_, HID_);
    // 9. out_y = y
    copy4_kernel<<<(M_*C_/4 + 255)/256, 256>>>((const float4*)y, (float4*)out_y, M_*C_/4);
}

// round 12
// speedup vs baseline: 1.4723x; 1.0922x over previous
#include <cuda_runtime.h>
#include <cuda_bf16.h>
#include <math.h>
#include <stdint.h>

// ---------------- problem constants ----------------
#define B_   4
#define NQ_  1024
#define NK_  1024
#define C_   768
#define H_   12
#define DH_  64
#define M_   (B_*NQ_)        // 4096
#define HID_ (4*C_)          // 3072
#define SCALE_ 0.125f

// ---------------- scratch (device globals; no allocation allowed) ----------------
__device__ __align__(256) float g_xn  [M_*C_];
__device__ __align__(256) float g_yn  [M_*C_];
__device__ __align__(256) float g_qkv [M_*3*C_];
__device__ __align__(256) float g_attn[M_*C_];
__device__ __align__(256) float g_x   [M_*C_];
__device__ __align__(256) float g_cq  [M_*C_];
__device__ __align__(256) float g_ck  [M_*C_];
__device__ __align__(256) float g_cv  [M_*C_];
__device__ __align__(256) float g_mean[M_*NK_];
__device__ __align__(256) float g_hbuf[M_*HID_];
__device__ __align__(256) __nv_bfloat16 g_ah[M_*HID_];
__device__ __align__(256) __nv_bfloat16 g_al[M_*HID_];
__device__ __align__(256) __nv_bfloat16 g_bh[HID_*C_];
__device__ __align__(256) __nv_bfloat16 g_bl[HID_*C_];

// ---------------- helpers ----------------
__device__ __forceinline__ uint32_t smem_u32(const void* p) {
    uint32_t a;
    asm("{ .reg .u64 t; cvta.to.shared.u64 t, %1; cvt.u32.u64 %0, t; }" : "=r"(a) : "l"(p));
    return a;
}
__device__ __forceinline__ void ldm_x4(uint32_t* r, uint32_t addr) {
    asm volatile("ldmatrix.sync.aligned.m8n8.x4.shared.b16 {%0,%1,%2,%3}, [%4];"
        : "=r"(r[0]), "=r"(r[1]), "=r"(r[2]), "=r"(r[3]) : "r"(addr));
}
__device__ __forceinline__ void mma_bf16(float* c, const uint32_t* a, const uint32_t* b) {
    asm volatile("mma.sync.aligned.m16n8k16.row.col.f32.bf16.bf16.f32 "
        "{%0,%1,%2,%3}, {%4,%5,%6,%7}, {%8,%9}, {%0,%1,%2,%3};"
        : "+f"(c[0]), "+f"(c[1]), "+f"(c[2]), "+f"(c[3])
        : "r"(a[0]), "r"(a[1]), "r"(a[2]), "r"(a[3]), "r"(b[0]), "r"(b[1]));
}
// packed f32x2 (Blackwell base ISA)
typedef unsigned long long u64t;
__device__ __forceinline__ u64t fma2(u64t a, u64t b, u64t c) {
    u64t d;
    asm("fma.rn.f32x2 %0, %1, %2, %3;" : "=l"(d) : "l"(a), "l"(b), "l"(c));
    return d;
}
__device__ __forceinline__ u64t mul2(u64t a, u64t b) {
    u64t d;
    asm("mul.rn.f32x2 %0, %1, %2;" : "=l"(d) : "l"(a), "l"(b));
    return d;
}
__device__ __forceinline__ u64t pack2(float lo, float hi) {
    u64t r;
    asm("mov.b64 %0, {%1, %2};" : "=l"(r) : "f"(lo), "f"(hi));
    return r;
}
__device__ __forceinline__ void unpack2(u64t v, float& lo, float& hi) {
    asm("mov.b64 {%0, %1}, %2;" : "=f"(lo), "=f"(hi) : "l"(v));
}
#define CP_ASYNC16(dst, src) \
    asm volatile("cp.async.cg.shared.global [%0], [%1], 16;" :: "r"(dst), "l"(src))
#define CP_COMMIT()  asm volatile("cp.async.commit_group;" ::: "memory")
#define CP_WAIT0()   asm volatile("cp.async.wait_group 0;" ::: "memory")

// ---------------- fp32 -> (hi,lo) bf16 split ----------------
__global__ __launch_bounds__(256) void cvt_split(const float* __restrict__ in,
                                                 __nv_bfloat16* __restrict__ hi,
                                                 __nv_bfloat16* __restrict__ lo, int n4)
{
    int i = blockIdx.x * 256 + threadIdx.x;
    if (i >= n4) return;
    float4 v = ((const float4*)in)[i];
    __nv_bfloat16 h0 = __float2bfloat16(v.x), h1 = __float2bfloat16(v.y);
    __nv_bfloat16 h2 = __float2bfloat16(v.z), h3 = __float2bfloat16(v.w);
    __nv_bfloat16 l0 = __float2bfloat16(v.x - __bfloat162float(h0));
    __nv_bfloat16 l1 = __float2bfloat16(v.y - __bfloat162float(h1));
    __nv_bfloat16 l2 = __float2bfloat16(v.z - __bfloat162float(h2));
    __nv_bfloat16 l3 = __float2bfloat16(v.w - __bfloat162float(h3));
    ((__nv_bfloat162*)hi)[2*i]   = __halves2bfloat162(h0, h1);
    ((__nv_bfloat162*)hi)[2*i+1] = __halves2bfloat162(h2, h3);
    ((__nv_bfloat162*)lo)[2*i]   = __halves2bfloat162(l0, l1);
    ((__nv_bfloat162*)lo)[2*i+1] = __halves2bfloat162(l2, l3);
}

// ---------------- HMMA split-bf16 GEMM NT, cp.async double-buffered -------------
#define BKP 40                      // padded row (elements); 80B rows, 16B-aligned
#define TILE_E (128 * BKP)          // elements per array per buffer
#define TILE_B (TILE_E * 2)         // bytes per array (10240)
#define BUF_B  (4 * TILE_B)         // bytes per buffer (40960)
#define TG_SMEM (2 * BUF_B)         // 81920

template<bool BIAS, bool RES, bool GELU>
__global__ __launch_bounds__(256) void tgemm(
    const __nv_bfloat16* __restrict__ Ah, const __nv_bfloat16* __restrict__ Al,
    const __nv_bfloat16* __restrict__ Bh, const __nv_bfloat16* __restrict__ Bl,
    const float* __restrict__ bias, const float* __restrict__ R,
    float* __restrict__ Cc, int M, int N, int K)
{
    extern __shared__ __align__(16) char smraw[];
    uint32_t u0 = smem_u32(smraw);

    int tid  = threadIdx.x;
    int wid  = tid >> 5, lane = tid & 31;
    int wm   = wid & 1;
    int wn   = wid >> 1;
    int bm = blockIdx.y * 128, bn = blockIdx.x * 128;

    float acc[4][4][4];
    #pragma unroll
    for (int i = 0; i < 4; i++)
        #pragma unroll
        for (int j = 0; j < 4; j++)
            #pragma unroll
            for (int q = 0; q < 4; q++) acc[i][j][q] = 0.f;

    // per-thread load slots: 8 x 16B
    int arow = lane & 15;
    int ahalf = (lane >> 4) << 3;

    const __nv_bfloat16* srcs[4] = {Ah, Al, Bh, Bl};

    // issue loads of tile kt into buffer buf
    auto load_tile = [&](int kt, int buf) {
        #pragma unroll
        for (int i = 0; i < 8; i++) {
            int idx = tid + i * 256;
            int a   = idx >> 9;
            int wi  = idx & 511;
            int row = wi >> 2, c = wi & 3;
            int gr = ((a < 2) ? bm : bn) + row;
            const __nv_bfloat16* src = srcs[a] + (size_t)gr * K + kt + c * 8;
            uint32_t dst = u0 + buf * BUF_B + a * TILE_B + (row * BKP + c * 8) * 2;
            CP_ASYNC16(dst, src);
        }
        CP_COMMIT();
    };

    load_tile(0, 0);
    CP_WAIT0();
    __syncthreads();

    int buf = 0;
    for (int kt = 0; kt < K; kt += 32) {
        bool more = (kt + 32 < K);
        if (more) load_tile(kt + 32, buf ^ 1);

        uint32_t uAh = u0 + buf * BUF_B;
        uint32_t uAl = uAh + TILE_B;
        uint32_t uBh = uAl + TILE_B;
        uint32_t uBl = uBh + TILE_B;

        #pragma unroll
        for (int ks = 0; ks < 32; ks += 16) {
            uint32_t ah[4][4], al[4][4];
            #pragma unroll
            for (int mt = 0; mt < 4; mt++) {
                uint32_t off = ((wm * 64 + mt * 16 + arow) * BKP + ks + ahalf) * 2;
                ldm_x4(ah[mt], uAh + off);
                ldm_x4(al[mt], uAl + off);
            }
            uint32_t bh[4][2], bl[4][2];
            #pragma unroll
            for (int nb = 0; nb < 2; nb++) {
                uint32_t off = ((wn * 32 + nb * 16 + arow) * BKP + ks + ahalf) * 2;
                uint32_t q[4];
                ldm_x4(q, uBh + off);
                bh[nb*2+0][0] = q[0]; bh[nb*2+0][1] = q[2];
                bh[nb*2+1][0] = q[1]; bh[nb*2+1][1] = q[3];
                ldm_x4(q, uBl + off);
                bl[nb*2+0][0] = q[0]; bl[nb*2+0][1] = q[2];
                bl[nb*2+1][0] = q[1]; bl[nb*2+1][1] = q[3];
            }
            #pragma unroll
            for (int mt = 0; mt < 4; mt++)
                #pragma unroll
                for (int nt = 0; nt < 4; nt++) {
                    mma_bf16(acc[mt][nt], ah[mt], bh[nt]);
                    mma_bf16(acc[mt][nt], ah[mt], bl[nt]);
                    mma_bf16(acc[mt][nt], al[mt], bh[nt]);
                }
        }
        if (more) {
            CP_WAIT0();
            __syncthreads();
            buf ^= 1;
        }
    }

    // ---- epilogue ----
    #pragma unroll
    for (int mt = 0; mt < 4; mt++) {
        #pragma unroll
        for (int nt = 0; nt < 4; nt++) {
            int m0 = bm + wm * 64 + mt * 16 + (lane >> 2);
            int n0 = bn + wn * 32 + nt * 8 + (lane & 3) * 2;
            #pragma unroll
            for (int half = 0; half < 2; half++) {
                int m = m0 + half * 8;
                float v0 = acc[mt][nt][half * 2 + 0];
                float v1 = acc[mt][nt][half * 2 + 1];
                if (BIAS) { v0 += bias[n0]; v1 += bias[n0 + 1]; }
                if (GELU) {
                    v0 = 0.5f * v0 * (1.0f + erff(v0 * 0.70710678118654752f));
                    v1 = 0.5f * v1 * (1.0f + erff(v1 * 0.70710678118654752f));
                }
                if (RES) {
                    v0 += R[(size_t)m * N + n0];
                    v1 += R[(size_t)m * N + n0 + 1];
                }
                *(float2*)(Cc + (size_t)m * N + n0) = make_float2(v0, v1);
            }
        }
    }
}

// ---------------- LayerNorm ----------------
__global__ __launch_bounds__(256) void ln_kernel(const float* __restrict__ in,
                                                 const float* __restrict__ gw,
                                                 const float* __restrict__ bw,
                                                 float* __restrict__ out)
{
    int row = blockIdx.x;
    const float* p = in + (size_t)row * C_;
    int t = threadIdx.x;
    float x0 = p[t], x1 = p[t + 256], x2 = p[t + 512];
    float s  = x0 + x1 + x2;
    float sq = x0*x0 + x1*x1 + x2*x2;
    #pragma unroll
    for (int o = 16; o > 0; o >>= 1) {
        s  += __shfl_xor_sync(0xffffffffu, s,  o);
        sq += __shfl_xor_sync(0xffffffffu, sq, o);
    }
    __shared__ float ss[8], sqs[8];
    __shared__ float s_mean, s_inv;
    int w = t >> 5, lane = t & 31;
    if (lane == 0) { ss[w] = s; sqs[w] = sq; }
    __syncthreads();
    if (t == 0) {
        float S = 0.f, SQ = 0.f;
        #pragma unroll
        for (int i = 0; i < 8; i++) { S += ss[i]; SQ += sqs[i]; }
        float mean = S * (1.0f / C_);
        float var  = SQ * (1.0f / C_) - mean * mean;
        s_mean = mean;
        s_inv  = rsqrtf(var + 1e-5f);
    }
    __syncthreads();
    float mean = s_mean, inv = s_inv;
    float* o = out + (size_t)row * C_;
    o[t]       = (x0 - mean) * inv * gw[t]       + bw[t];
    o[t + 256] = (x1 - mean) * inv * gw[t + 256] + bw[t + 256];
    o[t + 512] = (x2 - mean) * inv * gw[t + 512] + bw[t + 512];
}

// ---------------- head-mean of similarities ----------------
__global__ __launch_bounds__(256) void sim_mean_kernel(const float* __restrict__ sim,
                                                       float* __restrict__ meanb)
{
    int bq = blockIdx.x;
    int b  = bq >> 10;
    int q  = bq & 1023;
    for (int k = threadIdx.x; k < NK_; k += 256) {
        float s = 0.f;
        #pragma unroll
        for (int h = 0; h < H_; h++)
            s += sim[(((size_t)(b * H_ + h) * NQ_ + q) << 10) + k];
        meanb[((size_t)bq << 10) + k] = s * (1.0f / H_);
    }
}

// ---------------- self attention: packed f32x2 inner loop ----------------
__global__ __launch_bounds__(128) void attn_self_kernel(float* __restrict__ out)
{
    int qi = blockIdx.x * 128 + threadIdx.x;
    int h  = blockIdx.y, b = blockIdx.z;
    const float* qp = g_qkv + ((size_t)(b * NQ_ + qi)) * (3 * C_) + h * DH_;
    u64t q2[32];
    #pragma unroll
    for (int i = 0; i < 16; i++) {
        float4 v = *(const float4*)(qp + i * 4);
        q2[2*i]   = pack2(v.x * SCALE_, v.y * SCALE_);
        q2[2*i+1] = pack2(v.z * SCALE_, v.w * SCALE_);
    }
    __shared__ float Ks[64][64];
    __shared__ float Vs[64][64];
    u64t acc2[32];
    u64t zero = pack2(0.f, 0.f);
    #pragma unroll
    for (int d = 0; d < 32; d++) acc2[d] = zero;
    float m = -1e30f, l = 0.f;

    for (int k0 = 0; k0 < NK_; k0 += 64) {
        __syncthreads();
        #pragma unroll
        for (int i = 0; i < 8; i++) {
            int lin = threadIdx.x + i * 128;
            int r = lin >> 4, c = (lin & 15) << 2;
            const float* kp = g_qkv + ((size_t)(b * NQ_ + k0 + r)) * (3 * C_) + C_ + h * DH_ + c;
            *(float4*)&Ks[r][c] = *(const float4*)kp;
            *(float4*)&Vs[r][c] = *(const float4*)(kp + C_);
        }
        __syncthreads();
        for (int kk = 0; kk < 64; kk++) {
            u64t s01 = zero, s23 = zero;
            #pragma unroll
            for (int j = 0; j < 16; j++) {
                ulonglong2 kv = *(const ulonglong2*)&Ks[kk][j * 4];
                s01 = fma2(q2[2*j],   kv.x, s01);
                s23 = fma2(q2[2*j+1], kv.y, s23);
            }
            float a0, a1, a2, a3;
            unpack2(s01, a0, a1);
            unpack2(s23, a2, a3);
            float s = (a0 + a1) + (a2 + a3);
            float p;
            if (s > m) {
                float corr = __expf(m - s);
                l *= corr;
                u64t c2 = pack2(corr, corr);
                #pragma unroll
                for (int d = 0; d < 32; d++) acc2[d] = mul2(acc2[d], c2);
                m = s; p = 1.f;
            } else {
                p = __expf(s - m);
            }
            l += p;
            u64t pp = pack2(p, p);
            #pragma unroll
            for (int d = 0; d < 16; d++) {
                ulonglong2 vv = *(const ulonglong2*)&Vs[kk][d * 4];
                acc2[2*d]   = fma2(pp, vv.x, acc2[2*d]);
                acc2[2*d+1] = fma2(pp, vv.y, acc2[2*d+1]);
            }
        }
    }
    float inv = 1.f / l;
    float* op = out + ((size_t)(b * NQ_ + qi)) * C_ + h * DH_;
    #pragma unroll
    for (int d = 0; d < 16; d++) {
        float v0, v1, v2, v3;
        unpack2(acc2[2*d],   v0, v1);
        unpack2(acc2[2*d+1], v2, v3);
        *(float4*)(op + d * 4) = make_float4(v0 * inv, v1 * inv, v2 * inv, v3 * inv);
    }
}

// ---------------- cross attention (f32x2) with similarity bias + int32 mask -------
__global__ __launch_bounds__(128) void attn_cross_kernel(const float* __restrict__ sims,
                                                         const int* __restrict__ mask,
                                                         float* __restrict__ out)
{
    int qi = blockIdx.x * 128 + threadIdx.x;
    int h  = blockIdx.y, b = blockIdx.z;
    const float* qp = g_cq + ((size_t)(b * NQ_ + qi)) * C_ + h * DH_;
    u64t q2[32];
    #pragma unroll
    for (int i = 0; i < 16; i++) {
        float4 v = *(const float4*)(qp + i * 4);
        q2[2*i]   = pack2(v.x * SCALE_, v.y * SCALE_);
        q2[2*i+1] = pack2(v.z * SCALE_, v.w * SCALE_);
    }
    const float* simp  = sims  + ((size_t)(b * H_ + h) * NQ_ + qi) * NK_;
    const float* meanp = g_mean + ((size_t)(b * NQ_ + qi)) * NK_;
    const int*   maskp = mask + (size_t)qi * NK_;

    __shared__ float Ks[64][64];
    __shared__ float Vs[64][64];
    u64t acc2[32];
    u64t zero = pack2(0.f, 0.f);
    #pragma unroll
    for (int d = 0; d < 32; d++) acc2[d] = zero;
    float m = -1e30f, l = 0.f;

    for (int k0 = 0; k0 < NK_; k0 += 64) {
        __syncthreads();
        #pragma unroll
        for (int i = 0; i < 8; i++) {
            int lin = threadIdx.x + i * 128;
            int r = lin >> 4, c = (lin & 15) << 2;
            size_t roff = ((size_t)(b * NK_ + k0 + r)) * C_ + h * DH_ + c;
            *(float4*)&Ks[r][c] = *(const float4*)(g_ck + roff);
            *(float4*)&Vs[r][c] = *(const float4*)(g_cv + roff);
        }
        __syncthreads();
        for (int kk = 0; kk < 64; kk++) {
            int kidx = k0 + kk;
            u64t s01 = zero, s23 = zero;
            #pragma unroll
            for (int j = 0; j < 16; j++) {
                ulonglong2 kv = *(const ulonglong2*)&Ks[kk][j * 4];
                s01 = fma2(q2[2*j],   kv.x, s01);
                s23 = fma2(q2[2*j+1], kv.y, s23);
            }
            float a0, a1, a2, a3;
            unpack2(s01, a0, a1);
            unpack2(s23, a2, a3);
            float s = (a0 + a1) + (a2 + a3) + simp[kidx] - meanp[kidx];
            if (maskp[kidx] == 0) s = -1e30f;
            float p;
            if (s > m) {
                float corr = __expf(m - s);
                l *= corr;
                u64t c2 = pack2(corr, corr);
                #pragma unroll
                for (int d = 0; d < 32; d++) acc2[d] = mul2(acc2[d], c2);
                m = s; p = 1.f;
            } else {
                p = __expf(s - m);
            }
            l += p;
            u64t pp = pack2(p, p);
            #pragma unroll
            for (int d = 0; d < 16; d++) {
                ulonglong2 vv = *(const ulonglong2*)&Vs[kk][d * 4];
                acc2[2*d]   = fma2(pp, vv.x, acc2[2*d]);
                acc2[2*d+1] = fma2(pp, vv.y, acc2[2*d+1]);
            }
        }
    }
    float inv = 1.f / l;
    float* op = out + ((size_t)(b * NQ_ + qi)) * C_ + h * DH_;
    #pragma unroll
    for (int d = 0; d < 16; d++) {
        float v0, v1, v2, v3;
        unpack2(acc2[2*d],   v0, v1);
        unpack2(acc2[2*d+1], v2, v3);
        *(float4*)(op + d * 4) = make_float4(v0 * inv, v1 * inv, v2 * inv, v3 * inv);
    }
}

// ---------------- float4 copy ----------------
__global__ void copy4_kernel(const float4* __restrict__ in, float4* __restrict__ out, int n4)
{
    int i = blockIdx.x * 256 + threadIdx.x;
    if (i < n4) out[i] = in[i];
}

// ---------------- launch ----------------
static inline void cvt(const float* in, __nv_bfloat16* hi, __nv_bfloat16* lo, int n)
{
    int n4 = n / 4;
    cvt_split<<<n4 / 256, 256>>>(in, hi, lo, n4);
}

extern "C" void kernel_launch(void* const* d_in, const int* in_sizes, int n_in,
                              void* d_out, int out_size)
{
    const float* x      = (const float*)d_in[0];
    const float* y      = (const float*)d_in[1];
    const int*   mask   = (const int*)d_in[4];
    const float* sims   = (const float*)d_in[5];
    const float* ln1_g  = (const float*)d_in[6];
    const float* ln1_b  = (const float*)d_in[7];
    const float* ln2_g  = (const float*)d_in[8];
    const float* ln2_b  = (const float*)d_in[9];
    const float* ln3_g  = (const float*)d_in[10];
    const float* ln3_b  = (const float*)d_in[11];
    const float* lny_g  = (const float*)d_in[12];
    const float* lny_b  = (const float*)d_in[13];
    const float* qkv_w  = (const float*)d_in[14];
    const float* aproj_w= (const float*)d_in[15];
    const float* aproj_b= (const float*)d_in[16];
    const float* pq_w   = (const float*)d_in[17];
    const float* pk_w   = (const float*)d_in[18];
    const float* pv_w   = (const float*)d_in[19];
    const float* cproj_w= (const float*)d_in[20];
    const float* cproj_b= (const float*)d_in[21];
    const float* fc1_w  = (const float*)d_in[22];
    const float* fc1_b  = (const float*)d_in[23];
    const float* fc2_w  = (const float*)d_in[24];
    const float* fc2_b  = (const float*)d_in[25];

    float* out_x = (float*)d_out;
    float* out_y = out_x + (size_t)M_ * C_;

    float *xn, *yn, *qkv, *attn, *gx, *cq, *ck, *cv, *meanb, *hbuf;
    __nv_bfloat16 *ah, *al, *bh, *bl;
    cudaGetSymbolAddress((void**)&xn,    g_xn);
    cudaGetSymbolAddress((void**)&yn,    g_yn);
    cudaGetSymbolAddress((void**)&qkv,   g_qkv);
    cudaGetSymbolAddress((void**)&attn,  g_attn);
    cudaGetSymbolAddress((void**)&gx,    g_x);
    cudaGetSymbolAddress((void**)&cq,    g_cq);
    cudaGetSymbolAddress((void**)&ck,    g_ck);
    cudaGetSymbolAddress((void**)&cv,    g_cv);
    cudaGetSymbolAddress((void**)&meanb, g_mean);
    cudaGetSymbolAddress((void**)&hbuf,  g_hbuf);
    cudaGetSymbolAddress((void**)&ah,    g_ah);
    cudaGetSymbolAddress((void**)&al,    g_al);
    cudaGetSymbolAddress((void**)&bh,    g_bh);
    cudaGetSymbolAddress((void**)&bl,    g_bl);

    cudaFuncSetAttribute(tgemm<false,false,false>, cudaFuncAttributeMaxDynamicSharedMemorySize, TG_SMEM);
    cudaFuncSetAttribute(tgemm<true,true,false>,   cudaFuncAttributeMaxDynamicSharedMemorySize, TG_SMEM);
    cudaFuncSetAttribute(tgemm<true,false,true>,   cudaFuncAttributeMaxDynamicSharedMemorySize, TG_SMEM);

    // 1. xn = LN(x); qkv = xn @ qkv_w^T
    ln_kernel<<<M_, 256>>>(x, ln1_g, ln1_b, xn);
    cvt(xn, ah, al, M_ * C_);
    cvt(qkv_w, bh, bl, 3 * C_ * C_);
    tgemm<false,false,false><<<dim3(3*C_/128, M_/128), 256, TG_SMEM>>>(ah, al, bh, bl, nullptr, nullptr, qkv, M_, 3*C_, C_);
    // 2. self attention
    attn_self_kernel<<<dim3(NQ_/128, H_, B_), 128>>>(attn);
    // 3. gx = x + attn @ aproj_w^T + aproj_b
    cvt(attn, ah, al, M_ * C_);
    cvt(aproj_w, bh, bl, C_ * C_);
    tgemm<true,true,false><<<dim3(C_/128, M_/128), 256, TG_SMEM>>>(ah, al, bh, bl, aproj_b, x, gx, M_, C_, C_);
    // 4. norms
    ln_kernel<<<M_, 256>>>(y,  lny_g, lny_b, yn);
    ln_kernel<<<M_, 256>>>(gx, ln2_g, ln2_b, xn);
    // 5. cross projections
    cvt(xn, ah, al, M_ * C_);
    cvt(pq_w, bh, bl, C_ * C_);
    tgemm<false,false,false><<<dim3(C_/128, M_/128), 256, TG_SMEM>>>(ah, al, bh, bl, nullptr, nullptr, cq, M_, C_, C_);
    cvt(yn, ah, al, M_ * C_);
    cvt(pk_w, bh, bl, C_ * C_);
    tgemm<false,false,false><<<dim3(C_/128, M_/128), 256, TG_SMEM>>>(ah, al, bh, bl, nullptr, nullptr, ck, M_, C_, C_);
    cvt(pv_w, bh, bl, C_ * C_);
    tgemm<false,false,false><<<dim3(C_/128, M_/128), 256, TG_SMEM>>>(ah, al, bh, bl, nullptr, nullptr, cv, M_, C_, C_);
    // 6. cross attention
    sim_mean_kernel<<<M_, 256>>>(sims, meanb);
    attn_cross_kernel<<<dim3(NQ_/128, H_, B_), 128>>>(sims, mask, attn);
    // 7. gx = gx + attn @ cproj_w^T + cproj_b
    cvt(attn, ah, al, M_ * C_);
    cvt(cproj_w, bh, bl, C_ * C_);
    tgemm<true,true,false><<<dim3(C_/128, M_/128), 256, TG_SMEM>>>(ah, al, bh, bl, cproj_b, gx, gx, M_, C_, C_);
    // 8. MLP
    ln_kernel<<<M_, 256>>>(gx, ln3_g, ln3_b, xn);
    cvt(xn, ah, al, M_ * C_);
    cvt(fc1_w, bh, bl, HID_ * C_);
    tgemm<true,false,true><<<dim3(HID_/128, M_/128), 256, TG_SMEM>>>(ah, al, bh, bl, fc1_b, nullptr, hbuf, M_, HID_, C_);
    cvt(hbuf, ah, al, M_ * HID_);
    cvt(fc2_w, bh, bl, C_ * HID_);
    tgemm<true,true,false><<<dim3(C_/128, M_/128), 256, TG_SMEM>>>(ah, al, bh, bl, fc2_b, gx, out_x, M_, C_, HID_);
    // 9. out_y = y
    copy4_kernel<<<(M_*C_/4 + 255)/256, 256>>>((const float4*)y, (float4*)out_y, M_*C_/4);
}

// round 14
// speedup vs baseline: 2.1045x; 1.4294x over previous
#include <cuda_runtime.h>
#include <cuda_bf16.h>
#include <math.h>
#include <stdint.h>

// ---------------- problem constants ----------------
#define B_   4
#define NQ_  1024
#define NK_  1024
#define C_   768
#define H_   12
#define DH_  64
#define M_   (B_*NQ_)        // 4096
#define HID_ (4*C_)          // 3072
#define SCALE_ 0.125f

// ---------------- scratch (device globals; no allocation allowed) ----------------
__device__ __align__(256) float g_xn  [M_*C_];
__device__ __align__(256) float g_yn  [M_*C_];
__device__ __align__(256) float g_qkv [M_*3*C_];
__device__ __align__(256) float g_attn[M_*C_];
__device__ __align__(256) float g_x   [M_*C_];
__device__ __align__(256) float g_cq  [M_*C_];
__device__ __align__(256) float g_ck  [M_*C_];
__device__ __align__(256) float g_cv  [M_*C_];
__device__ __align__(256) float g_mean[M_*NK_];
__device__ __align__(256) float g_hbuf[M_*HID_];
__device__ __align__(256) __nv_bfloat16 g_ah[M_*HID_];
__device__ __align__(256) __nv_bfloat16 g_al[M_*HID_];
__device__ __align__(256) __nv_bfloat16 g_bh[HID_*C_];
__device__ __align__(256) __nv_bfloat16 g_bl[HID_*C_];

// ---------------- helpers ----------------
__device__ __forceinline__ uint32_t smem_u32(const void* p) {
    uint32_t a;
    asm("{ .reg .u64 t; cvta.to.shared.u64 t, %1; cvt.u32.u64 %0, t; }" : "=r"(a) : "l"(p));
    return a;
}
__device__ __forceinline__ void ldm_x4(uint32_t* r, uint32_t addr) {
    asm volatile("ldmatrix.sync.aligned.m8n8.x4.shared.b16 {%0,%1,%2,%3}, [%4];"
        : "=r"(r[0]), "=r"(r[1]), "=r"(r[2]), "=r"(r[3]) : "r"(addr));
}
__device__ __forceinline__ void mma_bf16(float* c, const uint32_t* a, const uint32_t* b) {
    asm volatile("mma.sync.aligned.m16n8k16.row.col.f32.bf16.bf16.f32 "
        "{%0,%1,%2,%3}, {%4,%5,%6,%7}, {%8,%9}, {%0,%1,%2,%3};"
        : "+f"(c[0]), "+f"(c[1]), "+f"(c[2]), "+f"(c[3])
        : "r"(a[0]), "r"(a[1]), "r"(a[2]), "r"(a[3]), "r"(b[0]), "r"(b[1]));
}
__device__ __forceinline__ uint32_t pack_bf(__nv_bfloat16 lo, __nv_bfloat16 hi) {
    __nv_bfloat162 t = __halves2bfloat162(lo, hi);
    return *(uint32_t*)&t;
}
#define CP_ASYNC16(dst, src) \
    asm volatile("cp.async.cg.shared.global [%0], [%1], 16;" :: "r"(dst), "l"(src))
#define CP_COMMIT()  asm volatile("cp.async.commit_group;" ::: "memory")
#define CP_WAIT0()   asm volatile("cp.async.wait_group 0;" ::: "memory")

// ---------------- fp32 -> (hi,lo) bf16 split ----------------
__global__ __launch_bounds__(256) void cvt_split(const float* __restrict__ in,
                                                 __nv_bfloat16* __restrict__ hi,
                                                 __nv_bfloat16* __restrict__ lo, int n4)
{
    int i = blockIdx.x * 256 + threadIdx.x;
    if (i >= n4) return;
    float4 v = ((const float4*)in)[i];
    __nv_bfloat16 h0 = __float2bfloat16(v.x), h1 = __float2bfloat16(v.y);
    __nv_bfloat16 h2 = __float2bfloat16(v.z), h3 = __float2bfloat16(v.w);
    __nv_bfloat16 l0 = __float2bfloat16(v.x - __bfloat162float(h0));
    __nv_bfloat16 l1 = __float2bfloat16(v.y - __bfloat162float(h1));
    __nv_bfloat16 l2 = __float2bfloat16(v.z - __bfloat162float(h2));
    __nv_bfloat16 l3 = __float2bfloat16(v.w - __bfloat162float(h3));
    ((__nv_bfloat162*)hi)[2*i]   = __halves2bfloat162(h0, h1);
    ((__nv_bfloat162*)hi)[2*i+1] = __halves2bfloat162(h2, h3);
    ((__nv_bfloat162*)lo)[2*i]   = __halves2bfloat162(l0, l1);
    ((__nv_bfloat162*)lo)[2*i+1] = __halves2bfloat162(l2, l3);
}

// ---------------- HMMA split-bf16 GEMM NT, cp.async double-buffered -------------
#define BKP 40
#define TILE_E (128 * BKP)
#define TILE_B (TILE_E * 2)
#define BUF_B  (4 * TILE_B)
#define TG_SMEM (2 * BUF_B)

template<bool BIAS, bool RES, bool GELU>
__global__ __launch_bounds__(256) void tgemm(
    const __nv_bfloat16* __restrict__ Ah, const __nv_bfloat16* __restrict__ Al,
    const __nv_bfloat16* __restrict__ Bh, const __nv_bfloat16* __restrict__ Bl,
    const float* __restrict__ bias, const float* __restrict__ R,
    float* __restrict__ Cc, int M, int N, int K)
{
    extern __shared__ __align__(16) char smraw[];
    uint32_t u0 = smem_u32(smraw);

    int tid  = threadIdx.x;
    int wid  = tid >> 5, lane = tid & 31;
    int wm   = wid & 1;
    int wn   = wid >> 1;
    int bm = blockIdx.y * 128, bn = blockIdx.x * 128;

    float acc[4][4][4];
    #pragma unroll
    for (int i = 0; i < 4; i++)
        #pragma unroll
        for (int j = 0; j < 4; j++)
            #pragma unroll
            for (int q = 0; q < 4; q++) acc[i][j][q] = 0.f;

    int arow = lane & 15;
    int ahalf = (lane >> 4) << 3;

    const __nv_bfloat16* srcs[4] = {Ah, Al, Bh, Bl};

    auto load_tile = [&](int kt, int buf) {
        #pragma unroll
        for (int i = 0; i < 8; i++) {
            int idx = tid + i * 256;
            int a   = idx >> 9;
            int wi  = idx & 511;
            int row = wi >> 2, c = wi & 3;
            int gr = ((a < 2) ? bm : bn) + row;
            const __nv_bfloat16* src = srcs[a] + (size_t)gr * K + kt + c * 8;
            uint32_t dst = u0 + buf * BUF_B + a * TILE_B + (row * BKP + c * 8) * 2;
            CP_ASYNC16(dst, src);
        }
        CP_COMMIT();
    };

    load_tile(0, 0);
    CP_WAIT0();
    __syncthreads();

    int buf = 0;
    for (int kt = 0; kt < K; kt += 32) {
        bool more = (kt + 32 < K);
        if (more) load_tile(kt + 32, buf ^ 1);

        uint32_t uAh = u0 + buf * BUF_B;
        uint32_t uAl = uAh + TILE_B;
        uint32_t uBh = uAl + TILE_B;
        uint32_t uBl = uBh + TILE_B;

        #pragma unroll
        for (int ks = 0; ks < 32; ks += 16) {
            uint32_t ah[4][4], al[4][4];
            #pragma unroll
            for (int mt = 0; mt < 4; mt++) {
                uint32_t off = ((wm * 64 + mt * 16 + arow) * BKP + ks + ahalf) * 2;
                ldm_x4(ah[mt], uAh + off);
                ldm_x4(al[mt], uAl + off);
            }
            uint32_t bh[4][2], bl[4][2];
            #pragma unroll
            for (int nb = 0; nb < 2; nb++) {
                uint32_t off = ((wn * 32 + nb * 16 + arow) * BKP + ks + ahalf) * 2;
                uint32_t q[4];
                ldm_x4(q, uBh + off);
                bh[nb*2+0][0] = q[0]; bh[nb*2+0][1] = q[2];
                bh[nb*2+1][0] = q[1]; bh[nb*2+1][1] = q[3];
                ldm_x4(q, uBl + off);
                bl[nb*2+0][0] = q[0]; bl[nb*2+0][1] = q[2];
                bl[nb*2+1][0] = q[1]; bl[nb*2+1][1] = q[3];
            }
            #pragma unroll
            for (int mt = 0; mt < 4; mt++)
                #pragma unroll
                for (int nt = 0; nt < 4; nt++) {
                    mma_bf16(acc[mt][nt], ah[mt], bh[nt]);
                    mma_bf16(acc[mt][nt], ah[mt], bl[nt]);
                    mma_bf16(acc[mt][nt], al[mt], bh[nt]);
                }
        }
        if (more) {
            CP_WAIT0();
            __syncthreads();
            buf ^= 1;
        }
    }

    #pragma unroll
    for (int mt = 0; mt < 4; mt++) {
        #pragma unroll
        for (int nt = 0; nt < 4; nt++) {
            int m0 = bm + wm * 64 + mt * 16 + (lane >> 2);
            int n0 = bn + wn * 32 + nt * 8 + (lane & 3) * 2;
            #pragma unroll
            for (int half = 0; half < 2; half++) {
                int m = m0 + half * 8;
                float v0 = acc[mt][nt][half * 2 + 0];
                float v1 = acc[mt][nt][half * 2 + 1];
                if (BIAS) { v0 += bias[n0]; v1 += bias[n0 + 1]; }
                if (GELU) {
                    v0 = 0.5f * v0 * (1.0f + erff(v0 * 0.70710678118654752f));
                    v1 = 0.5f * v1 * (1.0f + erff(v1 * 0.70710678118654752f));
                }
                if (RES) {
                    v0 += R[(size_t)m * N + n0];
                    v1 += R[(size_t)m * N + n0 + 1];
                }
                *(float2*)(Cc + (size_t)m * N + n0) = make_float2(v0, v1);
            }
        }
    }
}

// ---------------- HMMA flash attention (self & cross) ---------------------------
// CTA: 128 thr / 4 warps, 64 queries; key blocks of 64. Split-bf16 3-term MMA for
// both S = Q@K^T and O = P@V, fp32 softmax state per fragment row.
template<bool CROSS>
__global__ __launch_bounds__(128) void attn_mma(
    const float* __restrict__ Qb, const float* __restrict__ Kb, const float* __restrict__ Vb,
    int qstride, int kstride,
    const float* __restrict__ sims, const float* __restrict__ meanb,
    const int* __restrict__ mask,
    float* __restrict__ out)
{
    __shared__ __align__(16) __nv_bfloat16 sKh[64][72];
    __shared__ __align__(16) __nv_bfloat16 sKl[64][72];
    __shared__ __align__(16) __nv_bfloat16 sVh[64][72];   // transposed: [dh][key]
    __shared__ __align__(16) __nv_bfloat16 sVl[64][72];

    int tid = threadIdx.x;
    int w = tid >> 5, lane = tid & 31;
    int q0 = blockIdx.x * 64;
    int h = blockIdx.y, b = blockIdx.z;

    int arow = lane & 15, ahalf = (lane >> 4) << 3;

    // ---- load Q block (scaled, hi/lo) via staging smem, lift to A-fragments ----
    for (int i = tid; i < 1024; i += 128) {
        int row = i >> 4, c4 = (i & 15) << 2;
        const float* p = Qb + ((size_t)(b * NQ_ + q0 + row) * qstride + h * DH_ + c4);
        float4 v = *(const float4*)p;
        float f[4] = {v.x * SCALE_, v.y * SCALE_, v.z * SCALE_, v.w * SCALE_};
        #pragma unroll
        for (int e = 0; e < 4; e++) {
            __nv_bfloat16 hi = __float2bfloat16(f[e]);
            sKh[row][c4 + e] = hi;
            sKl[row][c4 + e] = __float2bfloat16(f[e] - __bfloat162float(hi));
        }
    }
    __syncthreads();
    uint32_t qh[4][4], ql[4][4];
    #pragma unroll
    for (int kc = 0; kc < 4; kc++) {
        ldm_x4(qh[kc], smem_u32(&sKh[w * 16 + arow][kc * 16 + ahalf]));
        ldm_x4(ql[kc], smem_u32(&sKl[w * 16 + arow][kc * 16 + ahalf]));
    }
    __syncthreads();

    int r  = lane >> 2;
    int cb = (lane & 3) * 2;
    int gq  = q0 + w * 16 + r;
    int gq8 = gq + 8;

    const float* simp0 = nullptr; const float* simp8 = nullptr;
    const float* mnp0 = nullptr;  const float* mnp8 = nullptr;
    const int* mk0 = nullptr;     const int* mk8 = nullptr;
    if (CROSS) {
        simp0 = sims  + ((size_t)((b * H_ + h) * NQ_ + gq)) * NK_;
        simp8 = simp0 + (size_t)8 * NK_;
        mnp0  = meanb + ((size_t)(b * NQ_ + gq)) * NK_;
        mnp8  = mnp0 + (size_t)8 * NK_;
        mk0   = mask + (size_t)gq * NK_;
        mk8   = mk0 + (size_t)8 * NK_;
    }

    float o[8][4];
    #pragma unroll
    for (int i = 0; i < 8; i++)
        #pragma unroll
        for (int j = 0; j < 4; j++) o[i][j] = 0.f;
    float m0 = -1e30f, m8 = -1e30f, l0 = 0.f, l8 = 0.f;

    for (int kb = 0; kb < NK_; kb += 64) {
        // ---- load K block (hi/lo) and V block transposed (hi/lo) ----
        for (int i = tid; i < 1024; i += 128) {
            int row = i >> 4, c4 = (i & 15) << 2;
            size_t ridx = (size_t)(b * NK_ + kb + row) * kstride + h * DH_ + c4;
            float4 kv = *(const float4*)(Kb + ridx);
            float kf[4] = {kv.x, kv.y, kv.z, kv.w};
            float4 vv = *(const float4*)(Vb + ridx);
            float vf[4] = {vv.x, vv.y, vv.z, vv.w};
            #pragma unroll
            for (int e = 0; e < 4; e++) {
                __nv_bfloat16 hi = __float2bfloat16(kf[e]);
                sKh[row][c4 + e] = hi;
                sKl[row][c4 + e] = __float2bfloat16(kf[e] - __bfloat162float(hi));
                __nv_bfloat16 vh = __float2bfloat16(vf[e]);
                sVh[c4 + e][row] = vh;
                sVl[c4 + e][row] = __float2bfloat16(vf[e] - __bfloat162float(vh));
            }
        }
        __syncthreads();

        // ---- S = Q @ K^T (3-term split) ----
        float sf[4][2][4];
        #pragma unroll
        for (int nt = 0; nt < 4; nt++)
            #pragma unroll
            for (int n8 = 0; n8 < 2; n8++)
                #pragma unroll
                for (int j = 0; j < 4; j++) sf[nt][n8][j] = 0.f;
        #pragma unroll
        for (int nt = 0; nt < 4; nt++) {
            #pragma unroll
            for (int kc = 0; kc < 4; kc++) {
                uint32_t qk[4], qk2[4];
                ldm_x4(qk,  smem_u32(&sKh[nt * 16 + arow][kc * 16 + ahalf]));
                ldm_x4(qk2, smem_u32(&sKl[nt * 16 + arow][kc * 16 + ahalf]));
                uint32_t bh0[2] = {qk[0], qk[2]},  bh1[2] = {qk[1], qk[3]};
                uint32_t bl0[2] = {qk2[0], qk2[2]}, bl1[2] = {qk2[1], qk2[3]};
                mma_bf16(sf[nt][0], qh[kc], bh0);
                mma_bf16(sf[nt][0], qh[kc], bl0);
                mma_bf16(sf[nt][0], ql[kc], bh0);
                mma_bf16(sf[nt][1], qh[kc], bh1);
                mma_bf16(sf[nt][1], qh[kc], bl1);
                mma_bf16(sf[nt][1], ql[kc], bh1);
            }
        }

        // ---- bias + mask (cross only) ----
        if (CROSS) {
            #pragma unroll
            for (int nt = 0; nt < 4; nt++)
                #pragma unroll
                for (int n8 = 0; n8 < 2; n8++) {
                    int col = kb + nt * 16 + n8 * 8 + cb;
                    float* f = sf[nt][n8];
                    f[0] += simp0[col]     - mnp0[col];
                    f[1] += simp0[col + 1] - mnp0[col + 1];
                    f[2] += simp8[col]     - mnp8[col];
                    f[3] += simp8[col + 1] - mnp8[col + 1];
                    if (mk0[col] == 0)     f[0] = -1e30f;
                    if (mk0[col + 1] == 0) f[1] = -1e30f;
                    if (mk8[col] == 0)     f[2] = -1e30f;
                    if (mk8[col + 1] == 0) f[3] = -1e30f;
                }
        }

        // ---- online softmax on fragments ----
        float bm0 = -1e30f, bm8 = -1e30f;
        #pragma unroll
        for (int nt = 0; nt < 4; nt++)
            #pragma unroll
            for (int n8 = 0; n8 < 2; n8++) {
                bm0 = fmaxf(bm0, fmaxf(sf[nt][n8][0], sf[nt][n8][1]));
                bm8 = fmaxf(bm8, fmaxf(sf[nt][n8][2], sf[nt][n8][3]));
            }
        bm0 = fmaxf(bm0, __shfl_xor_sync(0xffffffffu, bm0, 1));
        bm0 = fmaxf(bm0, __shfl_xor_sync(0xffffffffu, bm0, 2));
        bm8 = fmaxf(bm8, __shfl_xor_sync(0xffffffffu, bm8, 1));
        bm8 = fmaxf(bm8, __shfl_xor_sync(0xffffffffu, bm8, 2));
        float mn0 = fmaxf(m0, bm0), mn8 = fmaxf(m8, bm8);
        float c0 = __expf(m0 - mn0), c8 = __expf(m8 - mn8);
        m0 = mn0; m8 = mn8;
        l0 *= c0; l8 *= c8;
        #pragma unroll
        for (int i = 0; i < 8; i++) {
            o[i][0] *= c0; o[i][1] *= c0;
            o[i][2] *= c8; o[i][3] *= c8;
        }
        float rs0 = 0.f, rs8 = 0.f;
        uint32_t pah[4][4], pal[4][4];
        #pragma unroll
        for (int nt = 0; nt < 4; nt++) {
            #pragma unroll
            for (int n8 = 0; n8 < 2; n8++) {
                float p0 = __expf(sf[nt][n8][0] - m0);
                float p1 = __expf(sf[nt][n8][1] - m0);
                float p2 = __expf(sf[nt][n8][2] - m8);
                float p3 = __expf(sf[nt][n8][3] - m8);
                rs0 += p0 + p1; rs8 += p2 + p3;
                __nv_bfloat16 h0 = __float2bfloat16(p0), h1 = __float2bfloat16(p1);
                __nv_bfloat16 h2 = __float2bfloat16(p2), h3 = __float2bfloat16(p3);
                pah[nt][n8 * 2 + 0] = pack_bf(h0, h1);
                pah[nt][n8 * 2 + 1] = pack_bf(h2, h3);
                pal[nt][n8 * 2 + 0] = pack_bf(
                    __float2bfloat16(p0 - __bfloat162float(h0)),
                    __float2bfloat16(p1 - __bfloat162float(h1)));
                pal[nt][n8 * 2 + 1] = pack_bf(
                    __float2bfloat16(p2 - __bfloat162float(h2)),
                    __float2bfloat16(p3 - __bfloat162float(h3)));
            }
        }
        rs0 += __shfl_xor_sync(0xffffffffu, rs0, 1);
        rs0 += __shfl_xor_sync(0xffffffffu, rs0, 2);
        rs8 += __shfl_xor_sync(0xffffffffu, rs8, 1);
        rs8 += __shfl_xor_sync(0xffffffffu, rs8, 2);
        l0 += rs0; l8 += rs8;

        // ---- O += P @ V (3-term split) ----
        #pragma unroll
        for (int kc = 0; kc < 4; kc++) {
            #pragma unroll
            for (int nd = 0; nd < 4; nd++) {
                uint32_t qv[4], qv2[4];
                ldm_x4(qv,  smem_u32(&sVh[nd * 16 + arow][kc * 16 + ahalf]));
                ldm_x4(qv2, smem_u32(&sVl[nd * 16 + arow][kc * 16 + ahalf]));
                uint32_t vh0[2] = {qv[0], qv[2]},  vh1[2] = {qv[1], qv[3]};
                uint32_t vl0[2] = {qv2[0], qv2[2]}, vl1[2] = {qv2[1], qv2[3]};
                mma_bf16(o[nd * 2 + 0], pah[kc], vh0);
                mma_bf16(o[nd * 2 + 0], pah[kc], vl0);
                mma_bf16(o[nd * 2 + 0], pal[kc], vh0);
                mma_bf16(o[nd * 2 + 1], pah[kc], vh1);
                mma_bf16(o[nd * 2 + 1], pah[kc], vl1);
                mma_bf16(o[nd * 2 + 1], pal[kc], vh1);
            }
        }
        __syncthreads();
    }

    float i0 = 1.f / l0, i8 = 1.f / l8;
    float* op0 = out + ((size_t)(b * NQ_ + gq)  * C_ + h * DH_);
    float* op8 = out + ((size_t)(b * NQ_ + gq8) * C_ + h * DH_);
    #pragma unroll
    for (int nd8 = 0; nd8 < 8; nd8++) {
        int col = nd8 * 8 + cb;
        *(float2*)(op0 + col) = make_float2(o[nd8][0] * i0, o[nd8][1] * i0);
        *(float2*)(op8 + col) = make_float2(o[nd8][2] * i8, o[nd8][3] * i8);
    }
}

// ---------------- LayerNorm ----------------
__global__ __launch_bounds__(256) void ln_kernel(const float* __restrict__ in,
                                                 const float* __restrict__ gw,
                                                 const float* __restrict__ bw,
                                                 float* __restrict__ out)
{
    int row = blockIdx.x;
    const float* p = in + (size_t)row * C_;
    int t = threadIdx.x;
    float x0 = p[t], x1 = p[t + 256], x2 = p[t + 512];
    float s  = x0 + x1 + x2;
    float sq = x0*x0 + x1*x1 + x2*x2;
    #pragma unroll
    for (int o = 16; o > 0; o >>= 1) {
        s  += __shfl_xor_sync(0xffffffffu, s,  o);
        sq += __shfl_xor_sync(0xffffffffu, sq, o);
    }
    __shared__ float ss[8], sqs[8];
    __shared__ float s_mean, s_inv;
    int w = t >> 5, lane = t & 31;
    if (lane == 0) { ss[w] = s; sqs[w] = sq; }
    __syncthreads();
    if (t == 0) {
        float S = 0.f, SQ = 0.f;
        #pragma unroll
        for (int i = 0; i < 8; i++) { S += ss[i]; SQ += sqs[i]; }
        float mean = S * (1.0f / C_);
        float var  = SQ * (1.0f / C_) - mean * mean;
        s_mean = mean;
        s_inv  = rsqrtf(var + 1e-5f);
    }
    __syncthreads();
    float mean = s_mean, inv = s_inv;
    float* o = out + (size_t)row * C_;
    o[t]       = (x0 - mean) * inv * gw[t]       + bw[t];
    o[t + 256] = (x1 - mean) * inv * gw[t + 256] + bw[t + 256];
    o[t + 512] = (x2 - mean) * inv * gw[t + 512] + bw[t + 512];
}

// ---------------- head-mean of similarities ----------------
__global__ __launch_bounds__(256) void sim_mean_kernel(const float* __restrict__ sim,
                                                       float* __restrict__ meanb)
{
    int bq = blockIdx.x;
    int b  = bq >> 10;
    int q  = bq & 1023;
    for (int k = threadIdx.x; k < NK_; k += 256) {
        float s = 0.f;
        #pragma unroll
        for (int h = 0; h < H_; h++)
            s += sim[(((size_t)(b * H_ + h) * NQ_ + q) << 10) + k];
        meanb[((size_t)bq << 10) + k] = s * (1.0f / H_);
    }
}

// ---------------- float4 copy ----------------
__global__ void copy4_kernel(const float4* __restrict__ in, float4* __restrict__ out, int n4)
{
    int i = blockIdx.x * 256 + threadIdx.x;
    if (i < n4) out[i] = in[i];
}

// ---------------- launch ----------------
static inline void cvt(const float* in, __nv_bfloat16* hi, __nv_bfloat16* lo, int n)
{
    int n4 = n / 4;
    cvt_split<<<n4 / 256, 256>>>(in, hi, lo, n4);
}

extern "C" void kernel_launch(void* const* d_in, const int* in_sizes, int n_in,
                              void* d_out, int out_size)
{
    const float* x      = (const float*)d_in[0];
    const float* y      = (const float*)d_in[1];
    const int*   mask   = (const int*)d_in[4];
    const float* sims   = (const float*)d_in[5];
    const float* ln1_g  = (const float*)d_in[6];
    const float* ln1_b  = (const float*)d_in[7];
    const float* ln2_g  = (const float*)d_in[8];
    const float* ln2_b  = (const float*)d_in[9];
    const float* ln3_g  = (const float*)d_in[10];
    const float* ln3_b  = (const float*)d_in[11];
    const float* lny_g  = (const float*)d_in[12];
    const float* lny_b  = (const float*)d_in[13];
    const float* qkv_w  = (const float*)d_in[14];
    const float* aproj_w= (const float*)d_in[15];
    const float* aproj_b= (const float*)d_in[16];
    const float* pq_w   = (const float*)d_in[17];
    const float* pk_w   = (const float*)d_in[18];
    const float* pv_w   = (const float*)d_in[19];
    const float* cproj_w= (const float*)d_in[20];
    const float* cproj_b= (const float*)d_in[21];
    const float* fc1_w  = (const float*)d_in[22];
    const float* fc1_b  = (const float*)d_in[23];
    const float* fc2_w  = (const float*)d_in[24];
    const float* fc2_b  = (const float*)d_in[25];

    float* out_x = (float*)d_out;
    float* out_y = out_x + (size_t)M_ * C_;

    float *xn, *yn, *qkv, *attn, *gx, *cq, *ck, *cv, *meanb, *hbuf;
    __nv_bfloat16 *ah, *al, *bh, *bl;
    cudaGetSymbolAddress((void**)&xn,    g_xn);
    cudaGetSymbolAddress((void**)&yn,    g_yn);
    cudaGetSymbolAddress((void**)&qkv,   g_qkv);
    cudaGetSymbolAddress((void**)&attn,  g_attn);
    cudaGetSymbolAddress((void**)&gx,    g_x);
    cudaGetSymbolAddress((void**)&cq,    g_cq);
    cudaGetSymbolAddress((void**)&ck,    g_ck);
    cudaGetSymbolAddress((void**)&cv,    g_cv);
    cudaGetSymbolAddress((void**)&meanb, g_mean);
    cudaGetSymbolAddress((void**)&hbuf,  g_hbuf);
    cudaGetSymbolAddress((void**)&ah,    g_ah);
    cudaGetSymbolAddress((void**)&al,    g_al);
    cudaGetSymbolAddress((void**)&bh,    g_bh);
    cudaGetSymbolAddress((void**)&bl,    g_bl);

    cudaFuncSetAttribute(tgemm<false,false,false>, cudaFuncAttributeMaxDynamicSharedMemorySize, TG_SMEM);
    cudaFuncSetAttribute(tgemm<true,true,false>,   cudaFuncAttributeMaxDynamicSharedMemorySize, TG_SMEM);
    cudaFuncSetAttribute(tgemm<true,false,true>,   cudaFuncAttributeMaxDynamicSharedMemorySize, TG_SMEM);

    // 1. xn = LN(x); qkv = xn @ qkv_w^T
    ln_kernel<<<M_, 256>>>(x, ln1_g, ln1_b, xn);
    cvt(xn, ah, al, M_ * C_);
    cvt(qkv_w, bh, bl, 3 * C_ * C_);
    tgemm<false,false,false><<<dim3(3*C_/128, M_/128), 256, TG_SMEM>>>(ah, al, bh, bl, nullptr, nullptr, qkv, M_, 3*C_, C_);
    // 2. self attention (HMMA flash)
    attn_mma<false><<<dim3(NQ_/64, H_, B_), 128>>>(qkv, qkv + C_, qkv + 2*C_, 3*C_, 3*C_,
                                                   nullptr, nullptr, nullptr, attn);
    // 3. gx = x + attn @ aproj_w^T + aproj_b
    cvt(attn, ah, al, M_ * C_);
    cvt(aproj_w, bh, bl, C_ * C_);
    tgemm<true,true,false><<<dim3(C_/128, M_/128), 256, TG_SMEM>>>(ah, al, bh, bl, aproj_b, x, gx, M_, C_, C_);
    // 4. norms
    ln_kernel<<<M_, 256>>>(y,  lny_g, lny_b, yn);
    ln_kernel<<<M_, 256>>>(gx, ln2_g, ln2_b, xn);
    // 5. cross projections
    cvt(xn, ah, al, M_ * C_);
    cvt(pq_w, bh, bl, C_ * C_);
    tgemm<false,false,false><<<dim3(C_/128, M_/128), 256, TG_SMEM>>>(ah, al, bh, bl, nullptr, nullptr, cq, M_, C_, C_);
    cvt(yn, ah, al, M_ * C_);
    cvt(pk_w, bh, bl, C_ * C_);
    tgemm<false,false,false><<<dim3(C_/128, M_/128), 256, TG_SMEM>>>(ah, al, bh, bl, nullptr, nullptr, ck, M_, C_, C_);
    cvt(pv_w, bh, bl, C_ * C_);
    tgemm<false,false,false><<<dim3(C_/128, M_/128), 256, TG_SMEM>>>(ah, al, bh, bl, nullptr, nullptr, cv, M_, C_, C_);
    // 6. cross attention (HMMA flash)
    sim_mean_kernel<<<M_, 256>>>(sims, meanb);
    attn_mma<true><<<dim3(NQ_/64, H_, B_), 128>>>(cq, ck, cv, C_, C_,
                                                  sims, meanb, mask, attn);
    // 7. gx = gx + attn @ cproj_w^T + cproj_b
    cvt(attn, ah, al, M_ * C_);
    cvt(cproj_w, bh, bl, C_ * C_);
    tgemm<true,true,false><<<dim3(C_/128, M_/128), 256, TG_SMEM>>>(ah, al, bh, bl, cproj_b, gx, gx, M_, C_, C_);
    // 8. MLP
    ln_kernel<<<M_, 256>>>(gx, ln3_g, ln3_b, xn);
    cvt(xn, ah, al, M_ * C_);
    cvt(fc1_w, bh, bl, HID_ * C_);
    tgemm<true,false,true><<<dim3(HID_/128, M_/128), 256, TG_SMEM>>>(ah, al, bh, bl, fc1_b, nullptr, hbuf, M_, HID_, C_);
    cvt(hbuf, ah, al, M_ * HID_);
    cvt(fc2_w, bh, bl, C_ * HID_);
    tgemm<true,true,false><<<dim3(C_/128, M_/128), 256, TG_SMEM>>>(ah, al, bh, bl, fc2_b, gx, out_x, M_, C_, HID_);
    // 9. out_y = y
    copy4_kernel<<<(M_*C_/4 + 255)/256, 256>>>((const float4*)y, (float4*)out_y, M_*C_/4);
}